// round 2
// baseline (speedup 1.0000x reference)
#include <cuda_runtime.h>
#include <cstddef>

#define THREADS 128

// Shared layout (floats):
//   sW1  [128]            : W1[c][0][kh][kw] direct copy, float4 per channel
//   sb1  [32]
//   sW2  [2048]           : reordered [(c1*2+j)*32 + c2]
//   sb2  [32]
//   sWp  [4096]           : transposed [k*64 + o]
//   sbp  [64]
//   h2s  [64*THREADS]     : per-thread column staging of h2
#define SMEM_FLOATS (128 + 32 + 2048 + 32 + 4096 + 64 + 64 * THREADS)

__global__ __launch_bounds__(THREADS, 3)
void cnn_encoder_kernel(const float* __restrict__ x,
                        const float* __restrict__ W1, const float* __restrict__ b1,
                        const float* __restrict__ W2, const float* __restrict__ b2,
                        const float* __restrict__ Wp, const float* __restrict__ bp,
                        float* __restrict__ out)
{
    extern __shared__ float sm[];
    float* sW1 = sm;              // 128
    float* sb1 = sW1 + 128;       // 32
    float* sW2 = sb1 + 32;        // 2048
    float* sb2 = sW2 + 2048;      // 32
    float* sWp = sb2 + 32;        // 4096
    float* sbp = sWp + 4096;      // 64
    float* h2s = sbp + 64;        // 64*THREADS

    const int t = threadIdx.x;

    // ---- stage weights ----
    sW1[t] = W1[t];                       // 128 elems, 128 threads
    if (t < 32) { sb1[t] = b1[t]; sb2[t] = b2[t]; }
    if (t < 64) { sbp[t] = bp[t]; }
    #pragma unroll
    for (int i = t; i < 2048; i += THREADS) {
        int c2 = i >> 6;
        int r  = i & 63;
        int c1 = r >> 1;
        int j  = r & 1;
        sW2[(c1 * 2 + j) * 32 + c2] = W2[i];
    }
    #pragma unroll
    for (int i = t; i < 4096; i += THREADS) {
        int o = i >> 6;
        int k = i & 63;
        sWp[k * 64 + o] = Wp[i];
    }
    __syncthreads();

    const int row = blockIdx.x * THREADS + t;

    // ---- load input row (8 floats) ----
    const float4* xr = reinterpret_cast<const float4*>(x + (size_t)row * 8);
    float4 xa = xr[0];
    float4 xb = xr[1];
    const float x0 = xa.x, x1 = xa.y, x2 = xa.z, x3 = xa.w;
    const float x4 = xb.x, x5 = xb.y, x6 = xb.z, x7 = xb.w;

    // ---- conv2 accumulators, init with b2 ; layout acc[2*c2 + p] ----
    float acc[64];
    #pragma unroll
    for (int c2 = 0; c2 < 32; c2++) {
        float b = sb2[c2];
        acc[2 * c2]     = b;
        acc[2 * c2 + 1] = b;
    }

    // ---- fused conv1 + conv2 mainloop over input channels of conv2 ----
    #pragma unroll 2
    for (int c1 = 0; c1 < 32; c1++) {
        float4 w  = reinterpret_cast<const float4*>(sW1)[c1];
        float  bb = sb1[c1];
        // conv1 outputs at the 3 spatial positions, with bias+relu
        float h10 = fmaxf(bb + w.x * x0 + w.y * x1 + w.z * x4 + w.w * x5, 0.f);
        float h11 = fmaxf(bb + w.x * x1 + w.y * x2 + w.z * x5 + w.w * x6, 0.f);
        float h12 = fmaxf(bb + w.x * x2 + w.y * x3 + w.z * x6 + w.w * x7, 0.f);

        const float* w0p = sW2 + (c1 * 2) * 32;      // tap 0, all 32 c2
        const float* w1p = sW2 + (c1 * 2 + 1) * 32;  // tap 1
        #pragma unroll
        for (int c2 = 0; c2 < 32; c2 += 4) {
            float4 w0 = *reinterpret_cast<const float4*>(w0p + c2);
            float4 w1 = *reinterpret_cast<const float4*>(w1p + c2);
            acc[2 * c2 + 0] += w0.x * h10 + w1.x * h11;
            acc[2 * c2 + 1] += w0.x * h11 + w1.x * h12;
            acc[2 * c2 + 2] += w0.y * h10 + w1.y * h11;
            acc[2 * c2 + 3] += w0.y * h11 + w1.y * h12;
            acc[2 * c2 + 4] += w0.z * h10 + w1.z * h11;
            acc[2 * c2 + 5] += w0.z * h11 + w1.z * h12;
            acc[2 * c2 + 6] += w0.w * h10 + w1.w * h11;
            acc[2 * c2 + 7] += w0.w * h11 + w1.w * h12;
        }
    }

    // ---- relu, stage h2 in private smem column (same-thread r/w: no sync) ----
    #pragma unroll
    for (int k = 0; k < 64; k++) {
        h2s[k * THREADS + t] = fmaxf(acc[k], 0.f);
    }

    // ---- final linear: 64x64, computed in two halves of 32 outputs ----
    float* orow = out + (size_t)row * 64;
    #pragma unroll
    for (int half = 0; half < 2; half++) {
        float o_[32];
        #pragma unroll
        for (int o = 0; o < 32; o++) o_[o] = sbp[half * 32 + o];

        #pragma unroll 4
        for (int k = 0; k < 64; k++) {
            float hv = h2s[k * THREADS + t];
            const float* wp = sWp + k * 64 + half * 32;
            #pragma unroll
            for (int o4 = 0; o4 < 8; o4++) {
                float4 w = *reinterpret_cast<const float4*>(wp + 4 * o4);
                o_[4 * o4 + 0] += hv * w.x;
                o_[4 * o4 + 1] += hv * w.y;
                o_[4 * o4 + 2] += hv * w.z;
                o_[4 * o4 + 3] += hv * w.w;
            }
        }

        #pragma unroll
        for (int o4 = 0; o4 < 8; o4++) {
            float4 v = make_float4(o_[4 * o4 + 0], o_[4 * o4 + 1],
                                   o_[4 * o4 + 2], o_[4 * o4 + 3]);
            *reinterpret_cast<float4*>(orow + half * 32 + 4 * o4) = v;
        }
    }
}

extern "C" void kernel_launch(void* const* d_in, const int* in_sizes, int n_in,
                              void* d_out, int out_size)
{
    const float* x  = (const float*)d_in[0];
    const float* W1 = (const float*)d_in[1];
    const float* b1 = (const float*)d_in[2];
    const float* W2 = (const float*)d_in[3];
    const float* b2 = (const float*)d_in[4];
    const float* Wp = (const float*)d_in[5];
    const float* bp = (const float*)d_in[6];
    float* out = (float*)d_out;

    const int N = in_sizes[0] / 8;               // 524288 rows
    const int smem_bytes = SMEM_FLOATS * sizeof(float);  // ~58.4 KB

    // Not a stream operation: legal during graph capture, idempotent.
    cudaFuncSetAttribute(cnn_encoder_kernel,
                         cudaFuncAttributeMaxDynamicSharedMemorySize, smem_bytes);

    cnn_encoder_kernel<<<N / THREADS, THREADS, smem_bytes>>>(
        x, W1, b1, W2, b2, Wp, bp, out);
}

// round 3
// speedup vs baseline: 1.3233x; 1.3233x over previous
#include <cuda_runtime.h>
#include <cstddef>

#define THREADS 128

typedef unsigned long long ull;

// Packed f32x2 helpers (sm_103a FFMA2 path — only reachable via PTX fma.rn.f32x2)
static __device__ __forceinline__ ull pk2(float lo, float hi) {
    ull r; asm("mov.b64 %0, {%1, %2};" : "=l"(r) : "f"(lo), "f"(hi)); return r;
}
static __device__ __forceinline__ float2 upk2(ull v) {
    float2 r; asm("mov.b64 {%0, %1}, %2;" : "=f"(r.x), "=f"(r.y) : "l"(v)); return r;
}
#define FMA2(d, a, b) asm("fma.rn.f32x2 %0, %1, %2, %0;" : "+l"(d) : "l"(a), "l"(b))

// Shared layout (floats):
//   region0 (union, 8192 floats):
//     conv view: sW1[0:128) sb1[128:160) sb2[160:192) sW2[192:2240)
//     gemm view: At[64][128]  (h2 transposed: At[k][row_in_block])
//   region1: sWp[8192:12288) (k-major: [k*64+o]), sbp[12288:12352)
#define SMEM_FLOATS (8192 + 4096 + 64)

__global__ __launch_bounds__(THREADS, 4)
void cnn_encoder_kernel(const float* __restrict__ x,
                        const float* __restrict__ W1, const float* __restrict__ b1,
                        const float* __restrict__ W2, const float* __restrict__ b2,
                        const float* __restrict__ Wp, const float* __restrict__ bp,
                        float* __restrict__ out)
{
    extern __shared__ float sm[];
    float* sW1 = sm;           // 128
    float* sb1 = sm + 128;     // 32
    float* sb2 = sm + 160;     // 32
    float* sW2 = sm + 192;     // 2048, reordered [(c1*2+j)*32 + c2]
    float* At  = sm;           // overlay: 64 x 128
    float* sWp = sm + 8192;    // 4096, transposed [k*64 + o]
    float* sbp = sm + 12288;   // 64

    const int t = threadIdx.x;

    // ---- stage weights ----
    sW1[t] = W1[t];
    if (t < 32) { sb1[t] = b1[t]; sb2[t] = b2[t]; }
    if (t < 64) { sbp[t] = bp[t]; }
    #pragma unroll
    for (int i = t; i < 2048; i += THREADS) {
        int c2 = i >> 6, r = i & 63, c1 = r >> 1, j = r & 1;
        sW2[(c1 * 2 + j) * 32 + c2] = W2[i];
    }
    #pragma unroll
    for (int i = t; i < 4096; i += THREADS) {
        int o = i >> 6, k = i & 63;
        sWp[k * 64 + o] = Wp[i];
    }
    __syncthreads();

    const int row = blockIdx.x * THREADS + t;

    // ---- load input row ----
    const float4* xr = reinterpret_cast<const float4*>(x + (size_t)row * 8);
    float4 xa = xr[0], xb = xr[1];
    const float x0 = xa.x, x1 = xa.y, x2 = xa.z, x3 = xa.w;
    const float x4 = xb.x, x5 = xb.y, x6 = xb.z, x7 = xb.w;

    // ---- conv2 accumulators: packed over adjacent c2 pairs ----
    // accA[cp] = (h2pre[c2=2cp, p=0], h2pre[c2=2cp+1, p=0])
    // accB[cp] = same for p=1
    ull accA[16], accB[16];
    #pragma unroll
    for (int cp = 0; cp < 16; cp++) {
        ull b = *reinterpret_cast<const ull*>(sb2 + 2 * cp);
        accA[cp] = b;
        accB[cp] = b;
    }

    // ---- fused conv1 + conv2 (packed FFMA2) ----
    #pragma unroll 2
    for (int c1 = 0; c1 < 32; c1++) {
        float4 w  = reinterpret_cast<const float4*>(sW1)[c1];
        float  bb = sb1[c1];
        float h10 = fmaxf(bb + w.x * x0 + w.y * x1 + w.z * x4 + w.w * x5, 0.f);
        float h11 = fmaxf(bb + w.x * x1 + w.y * x2 + w.z * x5 + w.w * x6, 0.f);
        float h12 = fmaxf(bb + w.x * x2 + w.y * x3 + w.z * x6 + w.w * x7, 0.f);
        ull H0 = pk2(h10, h10), H1 = pk2(h11, h11), H2 = pk2(h12, h12);

        const ull* w0p = reinterpret_cast<const ull*>(sW2 + (c1 * 2) * 32);
        const ull* w1p = reinterpret_cast<const ull*>(sW2 + (c1 * 2 + 1) * 32);
        #pragma unroll
        for (int cp = 0; cp < 16; cp += 2) {
            ulonglong2 w0 = *reinterpret_cast<const ulonglong2*>(w0p + cp);
            ulonglong2 w1 = *reinterpret_cast<const ulonglong2*>(w1p + cp);
            FMA2(accA[cp],     w0.x, H0);  FMA2(accA[cp],     w1.x, H1);
            FMA2(accB[cp],     w0.x, H1);  FMA2(accB[cp],     w1.x, H2);
            FMA2(accA[cp + 1], w0.y, H0);  FMA2(accA[cp + 1], w1.y, H1);
            FMA2(accB[cp + 1], w0.y, H1);  FMA2(accB[cp + 1], w1.y, H2);
        }
    }

    __syncthreads();   // all threads done reading conv weights (region0)

    // ---- relu + stage h2 transposed: At[k=2*c2+p][t] ----
    #pragma unroll
    for (int cp = 0; cp < 16; cp++) {
        float2 a = upk2(accA[cp]);
        float2 b = upk2(accB[cp]);
        At[(4 * cp + 0) * THREADS + t] = fmaxf(a.x, 0.f);
        At[(4 * cp + 1) * THREADS + t] = fmaxf(b.x, 0.f);
        At[(4 * cp + 2) * THREADS + t] = fmaxf(a.y, 0.f);
        At[(4 * cp + 3) * THREADS + t] = fmaxf(b.y, 0.f);
    }
    __syncthreads();

    // ---- linear as register-tiled GEMM: [128 x 64] = At^T @ Wp^T ----
    // thread (i,j): rows i8..i8+7, outputs j8..j8+7, outputs packed in pairs.
    const int i8 = (t >> 3) * 8;
    const int j8 = (t & 7) * 8;

    ull acc[8][4];
    {
        const ull* bq = reinterpret_cast<const ull*>(sbp + j8);
        ull c0 = bq[0], c1_ = bq[1], c2_ = bq[2], c3_ = bq[3];
        #pragma unroll
        for (int r = 0; r < 8; r++) {
            acc[r][0] = c0; acc[r][1] = c1_; acc[r][2] = c2_; acc[r][3] = c3_;
        }
    }

    #pragma unroll 2
    for (int k = 0; k < 64; k++) {
        const float* arow = At + k * THREADS + i8;
        float4 a0 = *reinterpret_cast<const float4*>(arow);
        float4 a1 = *reinterpret_cast<const float4*>(arow + 4);
        const ulonglong2* brow = reinterpret_cast<const ulonglong2*>(sWp + k * 64 + j8);
        ulonglong2 b01 = brow[0], b23 = brow[1];

        ull A0 = pk2(a0.x, a0.x), A1 = pk2(a0.y, a0.y);
        ull A2 = pk2(a0.z, a0.z), A3 = pk2(a0.w, a0.w);
        ull A4 = pk2(a1.x, a1.x), A5 = pk2(a1.y, a1.y);
        ull A6 = pk2(a1.z, a1.z), A7 = pk2(a1.w, a1.w);

        FMA2(acc[0][0], A0, b01.x); FMA2(acc[0][1], A0, b01.y); FMA2(acc[0][2], A0, b23.x); FMA2(acc[0][3], A0, b23.y);
        FMA2(acc[1][0], A1, b01.x); FMA2(acc[1][1], A1, b01.y); FMA2(acc[1][2], A1, b23.x); FMA2(acc[1][3], A1, b23.y);
        FMA2(acc[2][0], A2, b01.x); FMA2(acc[2][1], A2, b01.y); FMA2(acc[2][2], A2, b23.x); FMA2(acc[2][3], A2, b23.y);
        FMA2(acc[3][0], A3, b01.x); FMA2(acc[3][1], A3, b01.y); FMA2(acc[3][2], A3, b23.x); FMA2(acc[3][3], A3, b23.y);
        FMA2(acc[4][0], A4, b01.x); FMA2(acc[4][1], A4, b01.y); FMA2(acc[4][2], A4, b23.x); FMA2(acc[4][3], A4, b23.y);
        FMA2(acc[5][0], A5, b01.x); FMA2(acc[5][1], A5, b01.y); FMA2(acc[5][2], A5, b23.x); FMA2(acc[5][3], A5, b23.y);
        FMA2(acc[6][0], A6, b01.x); FMA2(acc[6][1], A6, b01.y); FMA2(acc[6][2], A6, b23.x); FMA2(acc[6][3], A6, b23.y);
        FMA2(acc[7][0], A7, b01.x); FMA2(acc[7][1], A7, b01.y); FMA2(acc[7][2], A7, b23.x); FMA2(acc[7][3], A7, b23.y);
    }

    // ---- store 8x8 tile ----
    float* obase = out + (size_t)(blockIdx.x * THREADS + i8) * 64 + j8;
    #pragma unroll
    for (int r = 0; r < 8; r++) {
        float2 u0 = upk2(acc[r][0]), u1 = upk2(acc[r][1]);
        float2 u2 = upk2(acc[r][2]), u3 = upk2(acc[r][3]);
        *reinterpret_cast<float4*>(obase + r * 64)     = make_float4(u0.x, u0.y, u1.x, u1.y);
        *reinterpret_cast<float4*>(obase + r * 64 + 4) = make_float4(u2.x, u2.y, u3.x, u3.y);
    }
}

extern "C" void kernel_launch(void* const* d_in, const int* in_sizes, int n_in,
                              void* d_out, int out_size)
{
    const float* x  = (const float*)d_in[0];
    const float* W1 = (const float*)d_in[1];
    const float* b1 = (const float*)d_in[2];
    const float* W2 = (const float*)d_in[3];
    const float* b2 = (const float*)d_in[4];
    const float* Wp = (const float*)d_in[5];
    const float* bp = (const float*)d_in[6];
    float* out = (float*)d_out;

    const int N = in_sizes[0] / 8;                       // 524288 rows
    const int smem_bytes = SMEM_FLOATS * sizeof(float);  // 49408 B

    cudaFuncSetAttribute(cnn_encoder_kernel,
                         cudaFuncAttributeMaxDynamicSharedMemorySize, smem_bytes);

    cnn_encoder_kernel<<<N / THREADS, THREADS, smem_bytes>>>(
        x, W1, b1, W2, b2, Wp, bp, out);
}

// round 5
// speedup vs baseline: 1.4595x; 1.1029x over previous
#include <cuda_runtime.h>
#include <cuda_bf16.h>
#include <cstdint>
#include <cstddef>

#define THREADS 256
#define GRID    148
#define NTILES  4096          // 524288 rows / 128

// smem byte offsets
#define A1HI 0                // 128 rows x 208B (96 bf16 + pad)
#define A1LO 26624
#define A2HI 53248            // 128 rows x 144B (64 bf16 + pad)
#define A2LO 71680
#define CST  90112            // floats: W1[128], b1[32]
#define SMEM_BYTES (90112 + 160 * 4)
#define S1 208
#define S2 144

static __device__ __forceinline__ uint32_t smem_u32(const void* p) {
    uint32_t a;
    asm("{ .reg .u64 t; cvta.to.shared.u64 t, %1; cvt.u32.u64 %0, t; }" : "=r"(a) : "l"(p));
    return a;
}
static __device__ __forceinline__ void bsplit(float v, uint16_t& h, uint16_t& l) {
    __nv_bfloat16 bh = __float2bfloat16_rn(v);
    float vh = __bfloat162float(bh);
    __nv_bfloat16 bl = __float2bfloat16_rn(v - vh);
    h = reinterpret_cast<uint16_t&>(bh);
    l = reinterpret_cast<uint16_t&>(bl);
}
static __device__ __forceinline__ void bsplit2(float v0, float v1, uint32_t& hi, uint32_t& lo) {
    uint16_t h0, l0, h1, l1;
    bsplit(v0, h0, l0);
    bsplit(v1, h1, l1);
    hi = (uint32_t)h0 | ((uint32_t)h1 << 16);   // even-k element in low half
    lo = (uint32_t)l0 | ((uint32_t)l1 << 16);
}

#define LDSM4(r, addr) \
    asm volatile("ldmatrix.sync.aligned.m8n8.x4.shared.b16 {%0,%1,%2,%3}, [%4];" \
        : "=r"((r)[0]), "=r"((r)[1]), "=r"((r)[2]), "=r"((r)[3]) : "r"(addr))

#define MMA(d, a, b0, b1) \
    asm volatile("mma.sync.aligned.m16n8k16.row.col.f32.bf16.bf16.f32 " \
        "{%0,%1,%2,%3}, {%4,%5,%6,%7}, {%8,%9}, {%0,%1,%2,%3};" \
        : "+f"((d)[0]), "+f"((d)[1]), "+f"((d)[2]), "+f"((d)[3]) \
        : "r"((a)[0]), "r"((a)[1]), "r"((a)[2]), "r"((a)[3]), "r"(b0), "r"(b1))

__global__ __launch_bounds__(THREADS, 1)
void cnn_encoder_mma(const float* __restrict__ x,
                     const float* __restrict__ W1, const float* __restrict__ b1,
                     const float* __restrict__ W2, const float* __restrict__ b2,
                     const float* __restrict__ Wp, const float* __restrict__ bp,
                     float* __restrict__ out)
{
    extern __shared__ char smc[];
    const uint32_t sb = smem_u32(smc);
    float* cst = (float*)(smc + CST);   // W1[0:128) b1[128:160)

    const int t    = threadIdx.x;
    const int w    = t >> 5;
    const int lane = t & 31;
    const int g    = lane >> 2;   // group id (row/col within fragment)
    const int tg   = lane & 3;

    // ---- stage conv consts ----
    if (t < 128) cst[t] = W1[t];
    if (t < 32)  cst[128 + t] = b1[t];

    // ---- gather B fragments into registers (once) ----
    // GEMM1: B1[n][k] = densified W2'  (n = 2*c2+p, k = 3*c1+p+j, value W2[c2][c1][0][j])
    uint32_t b1h[6][2], b1l[6][2], b2h[4][2], b2l[4][2];
    {
        const int n1 = 8 * w + g;
        const int p  = n1 & 1;
        const int c2 = n1 >> 1;
        #pragma unroll
        for (int kt = 0; kt < 6; kt++) {
            #pragma unroll
            for (int rg = 0; rg < 2; rg++) {
                int k0 = kt * 16 + tg * 2 + rg * 8;
                float v0 = 0.f, v1 = 0.f;
                {
                    int d = k0 - p;
                    if (d >= 0) { int c1 = d / 3, q = d - 3 * c1; if (q < 2 && c1 < 32) v0 = W2[c2 * 64 + c1 * 2 + q]; }
                }
                {
                    int d = k0 + 1 - p;
                    int c1 = d / 3, q = d - 3 * c1;
                    if (q < 2 && c1 < 32) v1 = W2[c2 * 64 + c1 * 2 + q];
                }
                bsplit2(v0, v1, b1h[kt][rg], b1l[kt][rg]);
            }
        }
        const int o = 8 * w + g;
        #pragma unroll
        for (int kt = 0; kt < 4; kt++) {
            #pragma unroll
            for (int rg = 0; rg < 2; rg++) {
                int k0 = kt * 16 + tg * 2 + rg * 8;
                bsplit2(Wp[o * 64 + k0], Wp[o * 64 + k0 + 1], b2h[kt][rg], b2l[kt][rg]);
            }
        }
    }
    const float b2c = b2[4 * w + tg];          // bias for both D cols (n even, n+1 share c2)
    const float bp0 = bp[8 * w + tg * 2];
    const float bp1 = bp[8 * w + tg * 2 + 1];

    // ldmatrix per-lane base offsets: mat0 rows0-7/klo, mat1 rows8-15/klo, mat2 klo+8 ...
    const int mat  = lane >> 3;
    const int r8   = lane & 7;
    const int arow = r8 + 8 * (mat & 1);
    const int koff = 8 * (mat >> 1);
    const uint32_t a1b = sb + A1HI + arow * S1 + koff * 2;
    const uint32_t a2b = sb + A2HI + arow * S2 + koff * 2;

    const int row = t & 127;      // conv: row within tile
    const int h   = t >> 7;       // conv: which half of channels

    __syncthreads();

    for (int tile = blockIdx.x; tile < NTILES; tile += GRID) {
        // ================= conv1 -> A1 (bf16 hi/lo) =================
        {
            const float4* xr = (const float4*)(x + ((size_t)tile * 128 + row) * 8);
            float4 xa = xr[0], xb = xr[1];
            const float x0 = xa.x, x1 = xa.y, x2 = xa.z, x3 = xa.w;
            const float x4 = xb.x, x5 = xb.y, x6 = xb.z, x7 = xb.w;

            float hv[48];
            #pragma unroll
            for (int u = 0; u < 16; u++) {
                int c1 = 16 * h + u;
                float4 wv = ((const float4*)cst)[c1];
                float bb  = cst[128 + c1];
                hv[3 * u + 0] = fmaxf(bb + wv.x * x0 + wv.y * x1 + wv.z * x4 + wv.w * x5, 0.f);
                hv[3 * u + 1] = fmaxf(bb + wv.x * x1 + wv.y * x2 + wv.z * x5 + wv.w * x6, 0.f);
                hv[3 * u + 2] = fmaxf(bb + wv.x * x2 + wv.y * x3 + wv.z * x6 + wv.w * x7, 0.f);
            }
            #pragma unroll
            for (int b5 = 0; b5 < 6; b5++) {
                uint32_t uh[4], ul[4];
                #pragma unroll
                for (int j = 0; j < 4; j++)
                    bsplit2(hv[b5 * 8 + 2 * j], hv[b5 * 8 + 2 * j + 1], uh[j], ul[j]);
                char* p = smc + row * S1 + 96 * h + 16 * b5;     // k*2 bytes = 96h + 16*b5
                *(uint4*)(p + A1HI) = make_uint4(uh[0], uh[1], uh[2], uh[3]);
                *(uint4*)(p + A1LO) = make_uint4(ul[0], ul[1], ul[2], ul[3]);
            }
        }
        __syncthreads();

        // ================= GEMM1: [128x64] += A1[128x96] * B1^T =================
        float acc1[8][4];
        #pragma unroll
        for (int mt = 0; mt < 8; mt++)
            #pragma unroll
            for (int i = 0; i < 4; i++) acc1[mt][i] = 0.f;

        #pragma unroll
        for (int kt = 0; kt < 6; kt++) {
            #pragma unroll
            for (int mt = 0; mt < 8; mt++) {
                uint32_t ah[4], al[4];
                uint32_t ad = a1b + mt * (16 * S1) + kt * 32;
                LDSM4(ah, ad);
                LDSM4(al, ad + (A1LO - A1HI));
                MMA(acc1[mt], ah, b1h[kt][0], b1h[kt][1]);   // hi*hi
                MMA(acc1[mt], al, b1h[kt][0], b1h[kt][1]);   // lo*hi
                MMA(acc1[mt], ah, b1l[kt][0], b1l[kt][1]);   // hi*lo
            }
        }

        // ---- D1 epilogue: bias + relu -> A2 (bf16 hi/lo) ----
        {
            const int cb = (8 * w + tg * 2) * 2;   // byte offset of n-col pair
            #pragma unroll
            for (int mt = 0; mt < 8; mt++) {
                int r0 = mt * 16 + g, r1 = r0 + 8;
                float f00 = fmaxf(acc1[mt][0] + b2c, 0.f);
                float f01 = fmaxf(acc1[mt][1] + b2c, 0.f);
                float f10 = fmaxf(acc1[mt][2] + b2c, 0.f);
                float f11 = fmaxf(acc1[mt][3] + b2c, 0.f);
                uint32_t u0h, u0l, u1h, u1l;
                bsplit2(f00, f01, u0h, u0l);
                bsplit2(f10, f11, u1h, u1l);
                *(uint32_t*)(smc + A2HI + r0 * S2 + cb) = u0h;
                *(uint32_t*)(smc + A2LO + r0 * S2 + cb) = u0l;
                *(uint32_t*)(smc + A2HI + r1 * S2 + cb) = u1h;
                *(uint32_t*)(smc + A2LO + r1 * S2 + cb) = u1l;
            }
        }
        __syncthreads();

        // ================= GEMM2: [128x64] += A2[128x64] * Wp^T =================
        float acc2[8][4];
        #pragma unroll
        for (int mt = 0; mt < 8; mt++)
            #pragma unroll
            for (int i = 0; i < 4; i++) acc2[mt][i] = 0.f;

        #pragma unroll
        for (int kt = 0; kt < 4; kt++) {
            #pragma unroll
            for (int mt = 0; mt < 8; mt++) {
                uint32_t ah[4], al[4];
                uint32_t ad = a2b + mt * (16 * S2) + kt * 32;
                LDSM4(ah, ad);
                LDSM4(al, ad + (A2LO - A2HI));
                MMA(acc2[mt], ah, b2h[kt][0], b2h[kt][1]);
                MMA(acc2[mt], al, b2h[kt][0], b2h[kt][1]);
                MMA(acc2[mt], ah, b2l[kt][0], b2l[kt][1]);
            }
        }

        // ---- D2 epilogue: + bp -> out ----
        {
            const int ncol = 8 * w + tg * 2;
            #pragma unroll
            for (int mt = 0; mt < 8; mt++) {
                size_t r0 = (size_t)tile * 128 + mt * 16 + g;
                float2 v0 = make_float2(acc2[mt][0] + bp0, acc2[mt][1] + bp1);
                float2 v1 = make_float2(acc2[mt][2] + bp0, acc2[mt][3] + bp1);
                *(float2*)(out + r0 * 64 + ncol)       = v0;
                *(float2*)(out + (r0 + 8) * 64 + ncol) = v1;
            }
        }
        __syncthreads();   // protect A1/A2 before next tile's writes
    }
}

extern "C" void kernel_launch(void* const* d_in, const int* in_sizes, int n_in,
                              void* d_out, int out_size)
{
    const float* x  = (const float*)d_in[0];
    const float* W1 = (const float*)d_in[1];
    const float* b1 = (const float*)d_in[2];
    const float* W2 = (const float*)d_in[3];
    const float* b2 = (const float*)d_in[4];
    const float* Wp = (const float*)d_in[5];
    const float* bp = (const float*)d_in[6];
    float* out = (float*)d_out;

    cudaFuncSetAttribute(cnn_encoder_mma,
                         cudaFuncAttributeMaxDynamicSharedMemorySize, SMEM_BYTES);

    cnn_encoder_mma<<<GRID, THREADS, SMEM_BYTES>>>(x, W1, b1, W2, b2, Wp, bp, out);
}

// round 6
// speedup vs baseline: 2.1482x; 1.4719x over previous
#include <cuda_runtime.h>
#include <cuda_bf16.h>
#include <cstdint>
#include <cstddef>

#define THREADS 512
#define GRID    148
#define NTILES  4096          // 524288 rows / 128

// smem byte offsets
#define A1HI 0                // 128 x 208B (96 bf16 + pad)
#define A1LO 26624
#define A2HI 53248            // 128 x 144B (64 bf16 + pad)
#define A2LO 71680
#define B1HI 90112            // 64 x 208B (W2' densified, bf16)
#define B1LO 103424
#define B2HI 116736           // 64 x 144B (Wp)
#define B2LO 125952
#define CST  135168           // floats: W1[128], b1[32]
#define SMEM_BYTES (135168 + 160 * 4)
#define S1 208
#define S2 144

static __device__ __forceinline__ uint32_t smem_u32(const void* p) {
    uint32_t a;
    asm("{ .reg .u64 t; cvta.to.shared.u64 t, %1; cvt.u32.u64 %0, t; }" : "=r"(a) : "l"(p));
    return a;
}
static __device__ __forceinline__ void bsplit(float v, uint16_t& h, uint16_t& l) {
    __nv_bfloat16 bh = __float2bfloat16_rn(v);
    float vh = __bfloat162float(bh);
    __nv_bfloat16 bl = __float2bfloat16_rn(v - vh);
    h = reinterpret_cast<uint16_t&>(bh);
    l = reinterpret_cast<uint16_t&>(bl);
}
static __device__ __forceinline__ void bsplit2(float v0, float v1, uint32_t& hi, uint32_t& lo) {
    uint16_t h0, l0, h1, l1;
    bsplit(v0, h0, l0);
    bsplit(v1, h1, l1);
    hi = (uint32_t)h0 | ((uint32_t)h1 << 16);
    lo = (uint32_t)l0 | ((uint32_t)l1 << 16);
}

#define LDSM4(r, addr) \
    asm volatile("ldmatrix.sync.aligned.m8n8.x4.shared.b16 {%0,%1,%2,%3}, [%4];" \
        : "=r"((r)[0]), "=r"((r)[1]), "=r"((r)[2]), "=r"((r)[3]) : "r"(addr))

#define MMA(d, a, b0, b1) \
    asm volatile("mma.sync.aligned.m16n8k16.row.col.f32.bf16.bf16.f32 " \
        "{%0,%1,%2,%3}, {%4,%5,%6,%7}, {%8,%9}, {%0,%1,%2,%3};" \
        : "+f"((d)[0]), "+f"((d)[1]), "+f"((d)[2]), "+f"((d)[3]) \
        : "r"((a)[0]), "r"((a)[1]), "r"((a)[2]), "r"((a)[3]), "r"(b0), "r"(b1))

__global__ __launch_bounds__(THREADS, 1)
void cnn_encoder_mma2(const float* __restrict__ x,
                      const float* __restrict__ W1, const float* __restrict__ b1,
                      const float* __restrict__ W2, const float* __restrict__ b2,
                      const float* __restrict__ Wp, const float* __restrict__ bp,
                      float* __restrict__ out)
{
    extern __shared__ char smc[];
    const uint32_t sb = smem_u32(smc);
    float* cst = (float*)(smc + CST);   // W1[0:128) b1[128:160)

    const int t    = threadIdx.x;
    const int w    = t >> 5;
    const int lane = t & 31;
    const int g    = lane >> 2;
    const int tg   = lane & 3;
    const int wm   = w & 3;        // m-group: rows 32*wm .. +32
    const int wn   = w >> 2;       // n-group: cols 16*wn .. +16

    // ---- stage consts + B tiles (once) ----
    if (t < 128) cst[t] = W1[t];
    if (t < 32)  cst[128 + t] = b1[t];

    // B1' [n=64][k=96+pad] : n = 2*c2+p, k = 3*c1+s, val = W2[c2][c1][0][s-p] if 0<=s-p<=1
    for (int i = t; i < 64 * 104; i += THREADS) {
        int n = i / 104, kk = i - n * 104;
        float v = 0.f;
        if (kk < 96) {
            int p = n & 1, c2 = n >> 1;
            int d = kk - p;
            if (d >= 0) {
                int c1 = d / 3, q = d - 3 * c1;
                if (q < 2 && c1 < 32) v = W2[c2 * 64 + c1 * 2 + q];
            }
        }
        uint16_t h, l; bsplit(v, h, l);
        *(uint16_t*)(smc + B1HI + n * S1 + kk * 2) = h;
        *(uint16_t*)(smc + B1LO + n * S1 + kk * 2) = l;
    }
    // B2 [o=64][k=64+pad] = Wp
    for (int i = t; i < 64 * 72; i += THREADS) {
        int n = i / 72, kk = i - n * 72;
        float v = (kk < 64) ? Wp[n * 64 + kk] : 0.f;
        uint16_t h, l; bsplit(v, h, l);
        *(uint16_t*)(smc + B2HI + n * S2 + kk * 2) = h;
        *(uint16_t*)(smc + B2LO + n * S2 + kk * 2) = l;
    }

    // per-thread biases
    float b2v[2], bpv[2][2];
    #pragma unroll
    for (int nt = 0; nt < 2; nt++) {
        b2v[nt] = b2[8 * wn + 4 * nt + tg];
        bpv[nt][0] = bp[16 * wn + 8 * nt + 2 * tg];
        bpv[nt][1] = bp[16 * wn + 8 * nt + 2 * tg + 1];
    }

    // ldmatrix lane addressing (rows 0-15 / k halves pattern, same as validated R5)
    const int mat  = lane >> 3;
    const int lrow = (lane & 7) + 8 * (mat & 1);
    const int kby  = 16 * (mat >> 1);
    const uint32_t a1b = sb + A1HI + (32 * wm + lrow) * S1 + kby;
    const uint32_t a2b = sb + A2HI + (32 * wm + lrow) * S2 + kby;
    const uint32_t b1b = sb + B1HI + (16 * wn + lrow) * S1 + kby;
    const uint32_t b2b = sb + B2HI + (16 * wn + lrow) * S2 + kby;

    const int row = t & 127;      // conv: row within tile
    const int qh  = t >> 7;       // conv: quarter (8 channels each)

    __syncthreads();

    for (int tile = blockIdx.x; tile < NTILES; tile += GRID) {
        // ================= conv1 -> A1 (bf16 hi/lo) =================
        {
            const float4* xr = (const float4*)(x + ((size_t)tile * 128 + row) * 8);
            float4 xa = xr[0], xb = xr[1];
            const float x0 = xa.x, x1 = xa.y, x2 = xa.z, x3 = xa.w;
            const float x4 = xb.x, x5 = xb.y, x6 = xb.z, x7 = xb.w;

            float hv[24];
            #pragma unroll
            for (int u = 0; u < 8; u++) {
                int c1 = 8 * qh + u;
                float4 wv = ((const float4*)cst)[c1];
                float bb  = cst[128 + c1];
                hv[3 * u + 0] = fmaxf(bb + wv.x * x0 + wv.y * x1 + wv.z * x4 + wv.w * x5, 0.f);
                hv[3 * u + 1] = fmaxf(bb + wv.x * x1 + wv.y * x2 + wv.z * x5 + wv.w * x6, 0.f);
                hv[3 * u + 2] = fmaxf(bb + wv.x * x2 + wv.y * x3 + wv.z * x6 + wv.w * x7, 0.f);
            }
            #pragma unroll
            for (int b5 = 0; b5 < 3; b5++) {
                uint32_t uh[4], ul[4];
                #pragma unroll
                for (int j = 0; j < 4; j++)
                    bsplit2(hv[b5 * 8 + 2 * j], hv[b5 * 8 + 2 * j + 1], uh[j], ul[j]);
                char* p = smc + row * S1 + 48 * qh + 16 * b5;
                *(uint4*)(p + A1HI) = make_uint4(uh[0], uh[1], uh[2], uh[3]);
                *(uint4*)(p + A1LO) = make_uint4(ul[0], ul[1], ul[2], ul[3]);
            }
        }
        __syncthreads();

        // ================= GEMM1: [128x64] = A1[128x96] * B1^T =================
        float acc1[2][2][4];
        #pragma unroll
        for (int mt = 0; mt < 2; mt++)
            #pragma unroll
            for (int nt = 0; nt < 2; nt++)
                #pragma unroll
                for (int i = 0; i < 4; i++) acc1[mt][nt][i] = 0.f;

        #pragma unroll
        for (int kt = 0; kt < 6; kt++) {
            uint32_t bh[4], bl[4];
            LDSM4(bh, b1b + kt * 32);
            LDSM4(bl, b1b + kt * 32 + (B1LO - B1HI));
            #pragma unroll
            for (int mt = 0; mt < 2; mt++) {
                uint32_t ah[4], al[4];
                uint32_t ad = a1b + mt * (16 * S1) + kt * 32;
                LDSM4(ah, ad);
                LDSM4(al, ad + (A1LO - A1HI));
                #pragma unroll
                for (int nt = 0; nt < 2; nt++) {
                    MMA(acc1[mt][nt], ah, bh[nt], bh[nt + 2]);   // hi*hi
                    MMA(acc1[mt][nt], al, bh[nt], bh[nt + 2]);   // lo*hi
                    MMA(acc1[mt][nt], ah, bl[nt], bl[nt + 2]);   // hi*lo
                }
            }
        }

        // ---- D1 epilogue: bias + relu -> A2 (bf16 hi/lo) ----
        #pragma unroll
        for (int mt = 0; mt < 2; mt++) {
            #pragma unroll
            for (int nt = 0; nt < 2; nt++) {
                int r0 = 32 * wm + 16 * mt + g;
                int cb = (16 * wn + 8 * nt + 2 * tg) * 2;
                float f00 = fmaxf(acc1[mt][nt][0] + b2v[nt], 0.f);
                float f01 = fmaxf(acc1[mt][nt][1] + b2v[nt], 0.f);
                float f10 = fmaxf(acc1[mt][nt][2] + b2v[nt], 0.f);
                float f11 = fmaxf(acc1[mt][nt][3] + b2v[nt], 0.f);
                uint32_t u0h, u0l, u1h, u1l;
                bsplit2(f00, f01, u0h, u0l);
                bsplit2(f10, f11, u1h, u1l);
                *(uint32_t*)(smc + A2HI + r0 * S2 + cb)       = u0h;
                *(uint32_t*)(smc + A2LO + r0 * S2 + cb)       = u0l;
                *(uint32_t*)(smc + A2HI + (r0 + 8) * S2 + cb) = u1h;
                *(uint32_t*)(smc + A2LO + (r0 + 8) * S2 + cb) = u1l;
            }
        }
        __syncthreads();

        // ================= GEMM2: [128x64] = A2[128x64] * Wp^T =================
        float acc2[2][2][4];
        #pragma unroll
        for (int mt = 0; mt < 2; mt++)
            #pragma unroll
            for (int nt = 0; nt < 2; nt++)
                #pragma unroll
                for (int i = 0; i < 4; i++) acc2[mt][nt][i] = 0.f;

        #pragma unroll
        for (int kt = 0; kt < 4; kt++) {
            uint32_t bh[4], bl[4];
            LDSM4(bh, b2b + kt * 32);
            LDSM4(bl, b2b + kt * 32 + (B2LO - B2HI));
            #pragma unroll
            for (int mt = 0; mt < 2; mt++) {
                uint32_t ah[4], al[4];
                uint32_t ad = a2b + mt * (16 * S2) + kt * 32;
                LDSM4(ah, ad);
                LDSM4(al, ad + (A2LO - A2HI));
                #pragma unroll
                for (int nt = 0; nt < 2; nt++) {
                    MMA(acc2[mt][nt], ah, bh[nt], bh[nt + 2]);
                    MMA(acc2[mt][nt], al, bh[nt], bh[nt + 2]);
                    MMA(acc2[mt][nt], ah, bl[nt], bl[nt + 2]);
                }
            }
        }

        // ---- D2 epilogue: + bp -> out ----
        #pragma unroll
        for (int mt = 0; mt < 2; mt++) {
            #pragma unroll
            for (int nt = 0; nt < 2; nt++) {
                size_t r0 = (size_t)tile * 128 + 32 * wm + 16 * mt + g;
                int ncol = 16 * wn + 8 * nt + 2 * tg;
                float2 v0 = make_float2(acc2[mt][nt][0] + bpv[nt][0], acc2[mt][nt][1] + bpv[nt][1]);
                float2 v1 = make_float2(acc2[mt][nt][2] + bpv[nt][0], acc2[mt][nt][3] + bpv[nt][1]);
                *(float2*)(out + r0 * 64 + ncol)       = v0;
                *(float2*)(out + (r0 + 8) * 64 + ncol) = v1;
            }
        }
        __syncthreads();   // protect A1/A2 before next tile's writes
    }
}

extern "C" void kernel_launch(void* const* d_in, const int* in_sizes, int n_in,
                              void* d_out, int out_size)
{
    const float* x  = (const float*)d_in[0];
    const float* W1 = (const float*)d_in[1];
    const float* b1 = (const float*)d_in[2];
    const float* W2 = (const float*)d_in[3];
    const float* b2 = (const float*)d_in[4];
    const float* Wp = (const float*)d_in[5];
    const float* bp = (const float*)d_in[6];
    float* out = (float*)d_out;

    cudaFuncSetAttribute(cnn_encoder_mma2,
                         cudaFuncAttributeMaxDynamicSharedMemorySize, SMEM_BYTES);

    cnn_encoder_mma2<<<GRID, THREADS, SMEM_BYTES>>>(x, W1, b1, W2, b2, Wp, bp, out);
}

// round 7
// speedup vs baseline: 2.3183x; 1.0792x over previous
#include <cuda_runtime.h>
#include <cuda_bf16.h>
#include <cstdint>
#include <cstddef>

#define THREADS 256
#define GRID    296
#define NTILES  8192          // 524288 rows / 64

// smem byte offsets (per CTA, tile M=64)
#define A1HI 0                // 64 x 208B (96 bf16 + pad)
#define A1LO 13312
#define A2HI 26624            // 64 x 144B (64 bf16 + pad)
#define A2LO 35840
#define B1HI 45056            // 64 x 208B (W2' densified)
#define B1LO 58368
#define B2HI 71680            // 64 x 144B (Wp)
#define B2LO 80896
#define CST  90112            // floats: W1[128], b1[32]
#define SMEM_BYTES (90112 + 160 * 4)
#define S1 208
#define S2 144

static __device__ __forceinline__ uint32_t smem_u32(const void* p) {
    uint32_t a;
    asm("{ .reg .u64 t; cvta.to.shared.u64 t, %1; cvt.u32.u64 %0, t; }" : "=r"(a) : "l"(p));
    return a;
}
static __device__ __forceinline__ void bsplit(float v, uint16_t& h, uint16_t& l) {
    __nv_bfloat16 bh = __float2bfloat16_rn(v);
    float vh = __bfloat162float(bh);
    __nv_bfloat16 bl = __float2bfloat16_rn(v - vh);
    h = reinterpret_cast<uint16_t&>(bh);
    l = reinterpret_cast<uint16_t&>(bl);
}
static __device__ __forceinline__ void bsplit2(float v0, float v1, uint32_t& hi, uint32_t& lo) {
    uint16_t h0, l0, h1, l1;
    bsplit(v0, h0, l0);
    bsplit(v1, h1, l1);
    hi = (uint32_t)h0 | ((uint32_t)h1 << 16);
    lo = (uint32_t)l0 | ((uint32_t)l1 << 16);
}

#define LDSM4(r, addr) \
    asm volatile("ldmatrix.sync.aligned.m8n8.x4.shared.b16 {%0,%1,%2,%3}, [%4];" \
        : "=r"((r)[0]), "=r"((r)[1]), "=r"((r)[2]), "=r"((r)[3]) : "r"(addr))

#define MMA(d, a, b0, b1) \
    asm volatile("mma.sync.aligned.m16n8k16.row.col.f32.bf16.bf16.f32 " \
        "{%0,%1,%2,%3}, {%4,%5,%6,%7}, {%8,%9}, {%0,%1,%2,%3};" \
        : "+f"((d)[0]), "+f"((d)[1]), "+f"((d)[2]), "+f"((d)[3]) \
        : "r"((a)[0]), "r"((a)[1]), "r"((a)[2]), "r"((a)[3]), "r"(b0), "r"(b1))

__global__ __launch_bounds__(THREADS, 2)
void cnn_encoder_mma3(const float* __restrict__ x,
                      const float* __restrict__ W1, const float* __restrict__ b1,
                      const float* __restrict__ W2, const float* __restrict__ b2,
                      const float* __restrict__ Wp, const float* __restrict__ bp,
                      float* __restrict__ out)
{
    extern __shared__ char smc[];
    const uint32_t sb = smem_u32(smc);
    float* cst = (float*)(smc + CST);   // W1[0:128) b1[128:160)

    const int t    = threadIdx.x;
    const int w    = t >> 5;
    const int lane = t & 31;
    const int g    = lane >> 2;
    const int tg   = lane & 3;
    const int wm   = w & 1;        // m-group: rows 32*wm .. +32
    const int wn   = w >> 1;       // n-group: cols 16*wn .. +16

    // ---- stage consts + B tiles (once) ----
    if (t < 128) cst[t] = W1[t];
    if (t < 32)  cst[128 + t] = b1[t];

    // B1' [n=64][k=96+pad] : n = 2*c2+p, k = 3*c1+s, val = W2[c2][c1][0][s-p] if 0<=s-p<=1
    for (int i = t; i < 64 * 104; i += THREADS) {
        int n = i / 104, kk = i - n * 104;
        float v = 0.f;
        if (kk < 96) {
            int p = n & 1, c2 = n >> 1;
            int d = kk - p;
            if (d >= 0) {
                int c1 = d / 3, q = d - 3 * c1;
                if (q < 2 && c1 < 32) v = W2[c2 * 64 + c1 * 2 + q];
            }
        }
        uint16_t h, l; bsplit(v, h, l);
        *(uint16_t*)(smc + B1HI + n * S1 + kk * 2) = h;
        *(uint16_t*)(smc + B1LO + n * S1 + kk * 2) = l;
    }
    // B2 [o=64][k=64+pad] = Wp
    for (int i = t; i < 64 * 72; i += THREADS) {
        int n = i / 72, kk = i - n * 72;
        float v = (kk < 64) ? Wp[n * 64 + kk] : 0.f;
        uint16_t h, l; bsplit(v, h, l);
        *(uint16_t*)(smc + B2HI + n * S2 + kk * 2) = h;
        *(uint16_t*)(smc + B2LO + n * S2 + kk * 2) = l;
    }

    // per-thread biases
    float b2v[2], bpv[2][2];
    #pragma unroll
    for (int nt = 0; nt < 2; nt++) {
        b2v[nt] = b2[8 * wn + 4 * nt + tg];
        bpv[nt][0] = bp[16 * wn + 8 * nt + 2 * tg];
        bpv[nt][1] = bp[16 * wn + 8 * nt + 2 * tg + 1];
    }

    // ldmatrix lane addressing (same validated pattern)
    const int mat  = lane >> 3;
    const int lrow = (lane & 7) + 8 * (mat & 1);
    const int kby  = 16 * (mat >> 1);
    const uint32_t a1b = sb + A1HI + (32 * wm + lrow) * S1 + kby;
    const uint32_t a2b = sb + A2HI + (32 * wm + lrow) * S2 + kby;
    const uint32_t b1b = sb + B1HI + (16 * wn + lrow) * S1 + kby;
    const uint32_t b2b = sb + B2HI + (16 * wn + lrow) * S2 + kby;

    const int row = t & 63;       // conv: row within 64-row tile
    const int qh  = t >> 6;       // conv: quarter (8 channels each)

    __syncthreads();

    for (int tile = blockIdx.x; tile < NTILES; tile += GRID) {
        // ================= conv1 -> A1 (bf16 hi/lo) =================
        {
            const float4* xr = (const float4*)(x + ((size_t)tile * 64 + row) * 8);
            float4 xa = xr[0], xb = xr[1];
            const float x0 = xa.x, x1 = xa.y, x2 = xa.z, x3 = xa.w;
            const float x4 = xb.x, x5 = xb.y, x6 = xb.z, x7 = xb.w;

            float hv[24];
            #pragma unroll
            for (int u = 0; u < 8; u++) {
                int c1 = 8 * qh + u;
                float4 wv = ((const float4*)cst)[c1];
                float bb  = cst[128 + c1];
                hv[3 * u + 0] = fmaxf(bb + wv.x * x0 + wv.y * x1 + wv.z * x4 + wv.w * x5, 0.f);
                hv[3 * u + 1] = fmaxf(bb + wv.x * x1 + wv.y * x2 + wv.z * x5 + wv.w * x6, 0.f);
                hv[3 * u + 2] = fmaxf(bb + wv.x * x2 + wv.y * x3 + wv.z * x6 + wv.w * x7, 0.f);
            }
            #pragma unroll
            for (int b5 = 0; b5 < 3; b5++) {
                uint32_t uh[4], ul[4];
                #pragma unroll
                for (int j = 0; j < 4; j++)
                    bsplit2(hv[b5 * 8 + 2 * j], hv[b5 * 8 + 2 * j + 1], uh[j], ul[j]);
                char* p = smc + row * S1 + 48 * qh + 16 * b5;
                *(uint4*)(p + A1HI) = make_uint4(uh[0], uh[1], uh[2], uh[3]);
                *(uint4*)(p + A1LO) = make_uint4(ul[0], ul[1], ul[2], ul[3]);
            }
        }
        __syncthreads();

        // ================= GEMM1: [64x64] = A1[64x96] * B1^T =================
        float acc1[2][2][4];
        #pragma unroll
        for (int mt = 0; mt < 2; mt++)
            #pragma unroll
            for (int nt = 0; nt < 2; nt++)
                #pragma unroll
                for (int i = 0; i < 4; i++) acc1[mt][nt][i] = 0.f;

        #pragma unroll
        for (int kt = 0; kt < 6; kt++) {
            uint32_t bh[4], bl[4];
            LDSM4(bh, b1b + kt * 32);
            LDSM4(bl, b1b + kt * 32 + (B1LO - B1HI));
            #pragma unroll
            for (int mt = 0; mt < 2; mt++) {
                uint32_t ah[4], al[4];
                uint32_t ad = a1b + mt * (16 * S1) + kt * 32;
                LDSM4(ah, ad);
                LDSM4(al, ad + (A1LO - A1HI));
                #pragma unroll
                for (int nt = 0; nt < 2; nt++) {
                    MMA(acc1[mt][nt], ah, bh[nt], bh[nt + 2]);   // hi*hi
                    MMA(acc1[mt][nt], al, bh[nt], bh[nt + 2]);   // lo*hi
                    MMA(acc1[mt][nt], ah, bl[nt], bl[nt + 2]);   // hi*lo
                }
            }
        }

        // ---- D1 epilogue: bias + relu -> A2 (bf16 hi/lo) ----
        #pragma unroll
        for (int mt = 0; mt < 2; mt++) {
            #pragma unroll
            for (int nt = 0; nt < 2; nt++) {
                int r0 = 32 * wm + 16 * mt + g;
                int cb = (16 * wn + 8 * nt + 2 * tg) * 2;
                float f00 = fmaxf(acc1[mt][nt][0] + b2v[nt], 0.f);
                float f01 = fmaxf(acc1[mt][nt][1] + b2v[nt], 0.f);
                float f10 = fmaxf(acc1[mt][nt][2] + b2v[nt], 0.f);
                float f11 = fmaxf(acc1[mt][nt][3] + b2v[nt], 0.f);
                uint32_t u0h, u0l, u1h, u1l;
                bsplit2(f00, f01, u0h, u0l);
                bsplit2(f10, f11, u1h, u1l);
                *(uint32_t*)(smc + A2HI + r0 * S2 + cb)       = u0h;
                *(uint32_t*)(smc + A2LO + r0 * S2 + cb)       = u0l;
                *(uint32_t*)(smc + A2HI + (r0 + 8) * S2 + cb) = u1h;
                *(uint32_t*)(smc + A2LO + (r0 + 8) * S2 + cb) = u1l;
            }
        }
        __syncthreads();

        // ================= GEMM2: [64x64] = A2[64x64] * Wp^T =================
        float acc2[2][2][4];
        #pragma unroll
        for (int mt = 0; mt < 2; mt++)
            #pragma unroll
            for (int nt = 0; nt < 2; nt++)
                #pragma unroll
                for (int i = 0; i < 4; i++) acc2[mt][nt][i] = 0.f;

        #pragma unroll
        for (int kt = 0; kt < 4; kt++) {
            uint32_t bh[4], bl[4];
            LDSM4(bh, b2b + kt * 32);
            LDSM4(bl, b2b + kt * 32 + (B2LO - B2HI));
            #pragma unroll
            for (int mt = 0; mt < 2; mt++) {
                uint32_t ah[4], al[4];
                uint32_t ad = a2b + mt * (16 * S2) + kt * 32;
                LDSM4(ah, ad);
                LDSM4(al, ad + (A2LO - A2HI));
                #pragma unroll
                for (int nt = 0; nt < 2; nt++) {
                    MMA(acc2[mt][nt], ah, bh[nt], bh[nt + 2]);
                    MMA(acc2[mt][nt], al, bh[nt], bh[nt + 2]);
                    MMA(acc2[mt][nt], ah, bl[nt], bl[nt + 2]);
                }
            }
        }

        // ---- D2 epilogue: + bp -> out ----
        #pragma unroll
        for (int mt = 0; mt < 2; mt++) {
            #pragma unroll
            for (int nt = 0; nt < 2; nt++) {
                size_t r0 = (size_t)tile * 64 + 32 * wm + 16 * mt + g;
                int ncol = 16 * wn + 8 * nt + 2 * tg;
                float2 v0 = make_float2(acc2[mt][nt][0] + bpv[nt][0], acc2[mt][nt][1] + bpv[nt][1]);
                float2 v1 = make_float2(acc2[mt][nt][2] + bpv[nt][0], acc2[mt][nt][3] + bpv[nt][1]);
                *(float2*)(out + r0 * 64 + ncol)       = v0;
                *(float2*)(out + (r0 + 8) * 64 + ncol) = v1;
            }
        }
        __syncthreads();   // protect A1/A2 before next tile's writes
    }
}

extern "C" void kernel_launch(void* const* d_in, const int* in_sizes, int n_in,
                              void* d_out, int out_size)
{
    const float* x  = (const float*)d_in[0];
    const float* W1 = (const float*)d_in[1];
    const float* b1 = (const float*)d_in[2];
    const float* W2 = (const float*)d_in[3];
    const float* b2 = (const float*)d_in[4];
    const float* Wp = (const float*)d_in[5];
    const float* bp = (const float*)d_in[6];
    float* out = (float*)d_out;

    cudaFuncSetAttribute(cnn_encoder_mma3,
                         cudaFuncAttributeMaxDynamicSharedMemorySize, SMEM_BYTES);

    cnn_encoder_mma3<<<GRID, THREADS, SMEM_BYTES>>>(x, W1, b1, W2, b2, Wp, bp, out);
}

// round 8
// speedup vs baseline: 2.6742x; 1.1535x over previous
#include <cuda_runtime.h>
#include <cuda_bf16.h>
#include <cstdint>
#include <cstddef>

#define THREADS 256
#define GRID    296
#define NTILES  8192          // 524288 rows / 64

#define S 144                 // row stride (bytes) for all tiles, conflict-free
// smem byte offsets (per CTA, tile M=64)
#define AP0HI 0               // A0: 64 x 64 bf16 (h1 pos j)
#define AP0LO 9216
#define AP1HI 18432           // A1: 64 x 64 bf16 (h1 pos 1+j)
#define AP1LO 27648
#define A2HI  36864           // h2 parity-permuted: col = c2 + 32p
#define A2LO  46080
#define B1HI  55296           // W2 reshaped 32 x 64
#define B1LO  59904
#define B2HI  64512           // Wp column-permuted 64 x 64
#define B2LO  73728
#define CST   82944           // floats: W1[128], b1[32]
#define SMEM_BYTES (82944 + 160 * 4)

static __device__ __forceinline__ uint32_t smem_u32(const void* p) {
    uint32_t a;
    asm("{ .reg .u64 t; cvta.to.shared.u64 t, %1; cvt.u32.u64 %0, t; }" : "=r"(a) : "l"(p));
    return a;
}
static __device__ __forceinline__ void bsplit(float v, uint16_t& h, uint16_t& l) {
    __nv_bfloat16 bh = __float2bfloat16_rn(v);
    float vh = __bfloat162float(bh);
    __nv_bfloat16 bl = __float2bfloat16_rn(v - vh);
    h = reinterpret_cast<uint16_t&>(bh);
    l = reinterpret_cast<uint16_t&>(bl);
}
static __device__ __forceinline__ void bsplit2(float v0, float v1, uint32_t& hi, uint32_t& lo) {
    uint16_t h0, l0, h1, l1;
    bsplit(v0, h0, l0);
    bsplit(v1, h1, l1);
    hi = (uint32_t)h0 | ((uint32_t)h1 << 16);
    lo = (uint32_t)l0 | ((uint32_t)l1 << 16);
}

#define LDSM4(r, addr) \
    asm volatile("ldmatrix.sync.aligned.m8n8.x4.shared.b16 {%0,%1,%2,%3}, [%4];" \
        : "=r"((r)[0]), "=r"((r)[1]), "=r"((r)[2]), "=r"((r)[3]) : "r"(addr))

#define MMA(d, a, b0, b1) \
    asm volatile("mma.sync.aligned.m16n8k16.row.col.f32.bf16.bf16.f32 " \
        "{%0,%1,%2,%3}, {%4,%5,%6,%7}, {%8,%9}, {%0,%1,%2,%3};" \
        : "+f"((d)[0]), "+f"((d)[1]), "+f"((d)[2]), "+f"((d)[3]) \
        : "r"((a)[0]), "r"((a)[1]), "r"((a)[2]), "r"((a)[3]), "r"(b0), "r"(b1))

__global__ __launch_bounds__(THREADS, 2)
void cnn_encoder_mma4(const float* __restrict__ x,
                      const float* __restrict__ W1, const float* __restrict__ b1,
                      const float* __restrict__ W2, const float* __restrict__ b2,
                      const float* __restrict__ Wp, const float* __restrict__ bp,
                      float* __restrict__ out)
{
    extern __shared__ char smc[];
    const uint32_t sb = smem_u32(smc);
    float* cst = (float*)(smc + CST);   // W1[0:128) b1[128:160)

    const int t    = threadIdx.x;
    const int w    = t >> 5;
    const int lane = t & 31;
    const int g    = lane >> 2;
    const int tg   = lane & 3;
    // GEMM1 roles: parity group + 2m x 2n grid within it
    const int pg   = w >> 2;
    const int wm1  = w & 1;
    const int wn1  = (w >> 1) & 1;
    // GEMM2 roles: 2m x 4n grid (same as validated R7)
    const int wm2  = w & 1;
    const int wn2  = w >> 1;

    // ---- stage consts + B tiles (once) ----
    if (t < 128) cst[t] = W1[t];
    if (t < 32)  cst[128 + t] = b1[t];

    // B1 = W2 reshaped [c2=32][k=64], contiguous copy
    for (int i = t; i < 32 * 64; i += THREADS) {
        int c2 = i >> 6, kk = i & 63;
        uint16_t h, l; bsplit(W2[i], h, l);
        *(uint16_t*)(smc + B1HI + c2 * S + kk * 2) = h;
        *(uint16_t*)(smc + B1LO + c2 * S + kk * 2) = l;
    }
    // B2[o][kk] = Wp[o][2*(kk&31) + (kk>>5)]  (parity-permuted columns)
    for (int i = t; i < 64 * 64; i += THREADS) {
        int o = i >> 6, kk = i & 63;
        uint16_t h, l; bsplit(Wp[o * 64 + 2 * (kk & 31) + (kk >> 5)], h, l);
        *(uint16_t*)(smc + B2HI + o * S + kk * 2) = h;
        *(uint16_t*)(smc + B2LO + o * S + kk * 2) = l;
    }

    // per-thread biases
    float b2a[2], b2c[2], bpv[2][2];
    #pragma unroll
    for (int nt = 0; nt < 2; nt++) {
        b2a[nt] = b2[16 * wn1 + 8 * nt + 2 * tg];
        b2c[nt] = b2[16 * wn1 + 8 * nt + 2 * tg + 1];
        bpv[nt][0] = bp[16 * wn2 + 8 * nt + 2 * tg];
        bpv[nt][1] = bp[16 * wn2 + 8 * nt + 2 * tg + 1];
    }

    // ldmatrix lane addressing (validated pattern)
    const int mat  = lane >> 3;
    const int lrow = (lane & 7) + 8 * (mat & 1);
    const int kby  = 16 * (mat >> 1);
    const uint32_t a1b = sb + (pg ? AP1HI : AP0HI) + (32 * wm1 + lrow) * S + kby;
    const uint32_t b1b = sb + B1HI + (16 * wn1 + lrow) * S + kby;
    const uint32_t a2b = sb + A2HI + (32 * wm2 + lrow) * S + kby;
    const uint32_t b2b = sb + B2HI + (16 * wn2 + lrow) * S + kby;

    const int row = t & 63;       // conv: row within 64-row tile
    const int qh  = t >> 6;       // conv: 8-channel group 0..3

    __syncthreads();

    for (int tile = blockIdx.x; tile < NTILES; tile += GRID) {
        // ================= conv1 -> A0/A1 (bf16 hi/lo) =================
        {
            const float4* xr = (const float4*)(x + ((size_t)tile * 64 + row) * 8);
            float4 xa = xr[0], xb = xr[1];
            const float x0 = xa.x, x1 = xa.y, x2 = xa.z, x3 = xa.w;
            const float x4 = xb.x, x5 = xb.y, x6 = xb.z, x7 = xb.w;

            uint16_t hh[24], hl[24];
            #pragma unroll
            for (int u = 0; u < 8; u++) {
                int c1 = 8 * qh + u;
                float4 wv = ((const float4*)cst)[c1];
                float bb  = cst[128 + c1];
                float p0 = fmaxf(bb + wv.x * x0 + wv.y * x1 + wv.z * x4 + wv.w * x5, 0.f);
                float p1 = fmaxf(bb + wv.x * x1 + wv.y * x2 + wv.z * x5 + wv.w * x6, 0.f);
                float p2 = fmaxf(bb + wv.x * x2 + wv.y * x3 + wv.z * x6 + wv.w * x7, 0.f);
                bsplit(p0, hh[3 * u + 0], hl[3 * u + 0]);
                bsplit(p1, hh[3 * u + 1], hl[3 * u + 1]);
                bsplit(p2, hh[3 * u + 2], hl[3 * u + 2]);
            }
            // A0 col 2c1+j = pos j ; A1 col 2c1+j = pos 1+j  (local cols 16qh+2u+j)
            uint32_t a0h[8], a0l[8], a1h[8], a1l[8];
            #pragma unroll
            for (int u = 0; u < 8; u++) {
                a0h[u] = (uint32_t)hh[3 * u]     | ((uint32_t)hh[3 * u + 1] << 16);
                a0l[u] = (uint32_t)hl[3 * u]     | ((uint32_t)hl[3 * u + 1] << 16);
                a1h[u] = (uint32_t)hh[3 * u + 1] | ((uint32_t)hh[3 * u + 2] << 16);
                a1l[u] = (uint32_t)hl[3 * u + 1] | ((uint32_t)hl[3 * u + 2] << 16);
            }
            char* base = smc + row * S + 32 * qh;
            *(uint4*)(base + AP0HI)      = make_uint4(a0h[0], a0h[1], a0h[2], a0h[3]);
            *(uint4*)(base + AP0HI + 16) = make_uint4(a0h[4], a0h[5], a0h[6], a0h[7]);
            *(uint4*)(base + AP0LO)      = make_uint4(a0l[0], a0l[1], a0l[2], a0l[3]);
            *(uint4*)(base + AP0LO + 16) = make_uint4(a0l[4], a0l[5], a0l[6], a0l[7]);
            *(uint4*)(base + AP1HI)      = make_uint4(a1h[0], a1h[1], a1h[2], a1h[3]);
            *(uint4*)(base + AP1HI + 16) = make_uint4(a1h[4], a1h[5], a1h[6], a1h[7]);
            *(uint4*)(base + AP1LO)      = make_uint4(a1l[0], a1l[1], a1l[2], a1l[3]);
            *(uint4*)(base + AP1LO + 16) = make_uint4(a1l[4], a1l[5], a1l[6], a1l[7]);
        }
        __syncthreads();

        // ========= GEMM1 (parity pg): [64x32] = A_pg[64x64] * B1^T =========
        float acc1[2][2][4];
        #pragma unroll
        for (int mt = 0; mt < 2; mt++)
            #pragma unroll
            for (int nt = 0; nt < 2; nt++)
                #pragma unroll
                for (int i = 0; i < 4; i++) acc1[mt][nt][i] = 0.f;

        #pragma unroll
        for (int kt = 0; kt < 4; kt++) {
            uint32_t bh[4], bl[4];
            LDSM4(bh, b1b + kt * 32);
            LDSM4(bl, b1b + kt * 32 + (B1LO - B1HI));
            #pragma unroll
            for (int mt = 0; mt < 2; mt++) {
                uint32_t ah[4], al[4];
                uint32_t ad = a1b + mt * (16 * S) + kt * 32;
                LDSM4(ah, ad);
                LDSM4(al, ad + 9216);   // HI -> LO offset (both parities)
                #pragma unroll
                for (int nt = 0; nt < 2; nt++) {
                    MMA(acc1[mt][nt], ah, bh[nt], bh[nt + 2]);   // hi*hi
                    MMA(acc1[mt][nt], al, bh[nt], bh[nt + 2]);   // lo*hi
                    MMA(acc1[mt][nt], ah, bl[nt], bl[nt + 2]);   // hi*lo
                }
            }
        }

        // ---- D1 epilogue: bias + relu -> A2 (parity-permuted cols) ----
        #pragma unroll
        for (int mt = 0; mt < 2; mt++) {
            #pragma unroll
            for (int nt = 0; nt < 2; nt++) {
                int r0 = 32 * wm1 + 16 * mt + g;
                int cb = (32 * pg + 16 * wn1 + 8 * nt + 2 * tg) * 2;
                float f00 = fmaxf(acc1[mt][nt][0] + b2a[nt], 0.f);
                float f01 = fmaxf(acc1[mt][nt][1] + b2c[nt], 0.f);
                float f10 = fmaxf(acc1[mt][nt][2] + b2a[nt], 0.f);
                float f11 = fmaxf(acc1[mt][nt][3] + b2c[nt], 0.f);
                uint32_t u0h, u0l, u1h, u1l;
                bsplit2(f00, f01, u0h, u0l);
                bsplit2(f10, f11, u1h, u1l);
                *(uint32_t*)(smc + A2HI + r0 * S + cb)       = u0h;
                *(uint32_t*)(smc + A2LO + r0 * S + cb)       = u0l;
                *(uint32_t*)(smc + A2HI + (r0 + 8) * S + cb) = u1h;
                *(uint32_t*)(smc + A2LO + (r0 + 8) * S + cb) = u1l;
            }
        }
        __syncthreads();

        // ========= GEMM2: [64x64] = A2[64x64] * B2^T =========
        float acc2[2][2][4];
        #pragma unroll
        for (int mt = 0; mt < 2; mt++)
            #pragma unroll
            for (int nt = 0; nt < 2; nt++)
                #pragma unroll
                for (int i = 0; i < 4; i++) acc2[mt][nt][i] = 0.f;

        #pragma unroll
        for (int kt = 0; kt < 4; kt++) {
            uint32_t bh[4], bl[4];
            LDSM4(bh, b2b + kt * 32);
            LDSM4(bl, b2b + kt * 32 + (B2LO - B2HI));
            #pragma unroll
            for (int mt = 0; mt < 2; mt++) {
                uint32_t ah[4], al[4];
                uint32_t ad = a2b + mt * (16 * S) + kt * 32;
                LDSM4(ah, ad);
                LDSM4(al, ad + (A2LO - A2HI));
                #pragma unroll
                for (int nt = 0; nt < 2; nt++) {
                    MMA(acc2[mt][nt], ah, bh[nt], bh[nt + 2]);
                    MMA(acc2[mt][nt], al, bh[nt], bh[nt + 2]);
                    MMA(acc2[mt][nt], ah, bl[nt], bl[nt + 2]);
                }
            }
        }

        // ---- D2 epilogue: + bp -> out ----
        #pragma unroll
        for (int mt = 0; mt < 2; mt++) {
            #pragma unroll
            for (int nt = 0; nt < 2; nt++) {
                size_t r0 = (size_t)tile * 64 + 32 * wm2 + 16 * mt + g;
                int ncol = 16 * wn2 + 8 * nt + 2 * tg;
                float2 v0 = make_float2(acc2[mt][nt][0] + bpv[nt][0], acc2[mt][nt][1] + bpv[nt][1]);
                float2 v1 = make_float2(acc2[mt][nt][2] + bpv[nt][0], acc2[mt][nt][3] + bpv[nt][1]);
                *(float2*)(out + r0 * 64 + ncol)       = v0;
                *(float2*)(out + (r0 + 8) * 64 + ncol) = v1;
            }
        }
        __syncthreads();   // protect A tiles before next tile's writes
    }
}

extern "C" void kernel_launch(void* const* d_in, const int* in_sizes, int n_in,
                              void* d_out, int out_size)
{
    const float* x  = (const float*)d_in[0];
    const float* W1 = (const float*)d_in[1];
    const float* b1 = (const float*)d_in[2];
    const float* W2 = (const float*)d_in[3];
    const float* b2 = (const float*)d_in[4];
    const float* Wp = (const float*)d_in[5];
    const float* bp = (const float*)d_in[6];
    float* out = (float*)d_out;

    cudaFuncSetAttribute(cnn_encoder_mma4,
                         cudaFuncAttributeMaxDynamicSharedMemorySize, SMEM_BYTES);

    cnn_encoder_mma4<<<GRID, THREADS, SMEM_BYTES>>>(x, W1, b1, W2, b2, Wp, bp, out);
}

// round 9
// speedup vs baseline: 3.9343x; 1.4712x over previous
#include <cuda_runtime.h>
#include <cuda_fp16.h>
#include <cstdint>
#include <cstddef>

#define THREADS 256
#define GRID    444
#define NTILES  8192          // 524288 rows / 64

#define S 144                 // row stride (bytes), conflict-free
// smem byte offsets (per CTA, tile M=64) — A tiles single fp16, B tiles hi/lo
#define AP0   0               // A0: 64 x 64 fp16 (h1 pos j)
#define AP1   9216            // A1: 64 x 64 fp16 (h1 pos 1+j)
#define A2    18432           // h2 parity-permuted: col = c2 + 32p
#define B1HI  27648           // W2 reshaped 32 x 64
#define B1LO  32256
#define B2HI  36864           // Wp column-permuted 64 x 64
#define B2LO  46080
#define CST   55296           // floats: W1[128], b1[32]
#define SMEM_BYTES (55296 + 160 * 4)

static __device__ __forceinline__ uint32_t smem_u32(const void* p) {
    uint32_t a;
    asm("{ .reg .u64 t; cvta.to.shared.u64 t, %1; cvt.u32.u64 %0, t; }" : "=r"(a) : "l"(p));
    return a;
}
static __device__ __forceinline__ uint16_t h16(float v) {
    __half h = __float2half_rn(v);
    return reinterpret_cast<uint16_t&>(h);
}
static __device__ __forceinline__ void hsplit(float v, uint16_t& h, uint16_t& l) {
    __half hh = __float2half_rn(v);
    float vh = __half2float(hh);
    __half hl = __float2half_rn(v - vh);
    h = reinterpret_cast<uint16_t&>(hh);
    l = reinterpret_cast<uint16_t&>(hl);
}

#define LDSM4(r, addr) \
    asm volatile("ldmatrix.sync.aligned.m8n8.x4.shared.b16 {%0,%1,%2,%3}, [%4];" \
        : "=r"((r)[0]), "=r"((r)[1]), "=r"((r)[2]), "=r"((r)[3]) : "r"(addr))

#define MMA(d, a, b0, b1) \
    asm volatile("mma.sync.aligned.m16n8k16.row.col.f32.f16.f16.f32 " \
        "{%0,%1,%2,%3}, {%4,%5,%6,%7}, {%8,%9}, {%0,%1,%2,%3};" \
        : "+f"((d)[0]), "+f"((d)[1]), "+f"((d)[2]), "+f"((d)[3]) \
        : "r"((a)[0]), "r"((a)[1]), "r"((a)[2]), "r"((a)[3]), "r"(b0), "r"(b1))

__global__ __launch_bounds__(THREADS, 3)
void cnn_encoder_mma5(const float* __restrict__ x,
                      const float* __restrict__ W1, const float* __restrict__ b1,
                      const float* __restrict__ W2, const float* __restrict__ b2,
                      const float* __restrict__ Wp, const float* __restrict__ bp,
                      float* __restrict__ out)
{
    extern __shared__ char smc[];
    const uint32_t sb = smem_u32(smc);
    float* cst = (float*)(smc + CST);   // W1[0:128) b1[128:160)

    const int t    = threadIdx.x;
    const int w    = t >> 5;
    const int lane = t & 31;
    const int g    = lane >> 2;
    const int tg   = lane & 3;
    // GEMM1 roles: parity group + 2m x 2n grid within it
    const int pg   = w >> 2;
    const int wm1  = w & 1;
    const int wn1  = (w >> 1) & 1;
    // GEMM2 roles: 2m x 4n grid
    const int wm2  = w & 1;
    const int wn2  = w >> 1;

    // ---- stage consts + B tiles (once) ----
    if (t < 128) cst[t] = W1[t];
    if (t < 32)  cst[128 + t] = b1[t];

    // B1 = W2 reshaped [c2=32][k=64], fp16 hi/lo
    for (int i = t; i < 32 * 64; i += THREADS) {
        int c2 = i >> 6, kk = i & 63;
        uint16_t h, l; hsplit(W2[i], h, l);
        *(uint16_t*)(smc + B1HI + c2 * S + kk * 2) = h;
        *(uint16_t*)(smc + B1LO + c2 * S + kk * 2) = l;
    }
    // B2[o][kk] = Wp[o][2*(kk&31) + (kk>>5)]  (parity-permuted columns), fp16 hi/lo
    for (int i = t; i < 64 * 64; i += THREADS) {
        int o = i >> 6, kk = i & 63;
        uint16_t h, l; hsplit(Wp[o * 64 + 2 * (kk & 31) + (kk >> 5)], h, l);
        *(uint16_t*)(smc + B2HI + o * S + kk * 2) = h;
        *(uint16_t*)(smc + B2LO + o * S + kk * 2) = l;
    }

    // per-thread biases
    float b2a[2], b2c[2], bpv[2][2];
    #pragma unroll
    for (int nt = 0; nt < 2; nt++) {
        b2a[nt] = b2[16 * wn1 + 8 * nt + 2 * tg];
        b2c[nt] = b2[16 * wn1 + 8 * nt + 2 * tg + 1];
        bpv[nt][0] = bp[16 * wn2 + 8 * nt + 2 * tg];
        bpv[nt][1] = bp[16 * wn2 + 8 * nt + 2 * tg + 1];
    }

    // ldmatrix lane addressing (validated pattern)
    const int mat  = lane >> 3;
    const int lrow = (lane & 7) + 8 * (mat & 1);
    const int kby  = 16 * (mat >> 1);
    const uint32_t a1b = sb + (pg ? AP1 : AP0) + (32 * wm1 + lrow) * S + kby;
    const uint32_t b1b = sb + B1HI + (16 * wn1 + lrow) * S + kby;
    const uint32_t a2b = sb + A2 + (32 * wm2 + lrow) * S + kby;
    const uint32_t b2b = sb + B2HI + (16 * wn2 + lrow) * S + kby;

    const int row = t & 63;       // conv: row within 64-row tile
    const int qh  = t >> 6;       // conv: 8-channel group 0..3

    __syncthreads();

    for (int tile = blockIdx.x; tile < NTILES; tile += GRID) {
        // ================= conv1 -> A0/A1 (single fp16) =================
        {
            const float4* xr = (const float4*)(x + ((size_t)tile * 64 + row) * 8);
            float4 xa = xr[0], xb = xr[1];
            const float x0 = xa.x, x1 = xa.y, x2 = xa.z, x3 = xa.w;
            const float x4 = xb.x, x5 = xb.y, x6 = xb.z, x7 = xb.w;

            uint32_t a0[8], a1[8];
            #pragma unroll
            for (int u = 0; u < 8; u++) {
                int c1 = 8 * qh + u;
                float4 wv = ((const float4*)cst)[c1];
                float bb  = cst[128 + c1];
                float p0 = fmaxf(bb + wv.x * x0 + wv.y * x1 + wv.z * x4 + wv.w * x5, 0.f);
                float p1 = fmaxf(bb + wv.x * x1 + wv.y * x2 + wv.z * x5 + wv.w * x6, 0.f);
                float p2 = fmaxf(bb + wv.x * x2 + wv.y * x3 + wv.z * x6 + wv.w * x7, 0.f);
                uint16_t q0 = h16(p0), q1 = h16(p1), q2 = h16(p2);
                a0[u] = (uint32_t)q0 | ((uint32_t)q1 << 16);   // A0 pair (p0,p1)
                a1[u] = (uint32_t)q1 | ((uint32_t)q2 << 16);   // A1 pair (p1,p2)
            }
            char* base = smc + row * S + 32 * qh;
            *(uint4*)(base + AP0)      = make_uint4(a0[0], a0[1], a0[2], a0[3]);
            *(uint4*)(base + AP0 + 16) = make_uint4(a0[4], a0[5], a0[6], a0[7]);
            *(uint4*)(base + AP1)      = make_uint4(a1[0], a1[1], a1[2], a1[3]);
            *(uint4*)(base + AP1 + 16) = make_uint4(a1[4], a1[5], a1[6], a1[7]);
        }
        __syncthreads();

        // ========= GEMM1 (parity pg): [64x32] = A_pg[64x64] * B1^T =========
        float acc1[2][2][4];
        #pragma unroll
        for (int mt = 0; mt < 2; mt++)
            #pragma unroll
            for (int nt = 0; nt < 2; nt++)
                #pragma unroll
                for (int i = 0; i < 4; i++) acc1[mt][nt][i] = 0.f;

        #pragma unroll
        for (int kt = 0; kt < 4; kt++) {
            uint32_t bh[4], bl[4];
            LDSM4(bh, b1b + kt * 32);
            LDSM4(bl, b1b + kt * 32 + (B1LO - B1HI));
            #pragma unroll
            for (int mt = 0; mt < 2; mt++) {
                uint32_t ah[4];
                LDSM4(ah, a1b + mt * (16 * S) + kt * 32);
                #pragma unroll
                for (int nt = 0; nt < 2; nt++) {
                    MMA(acc1[mt][nt], ah, bh[nt], bh[nt + 2]);   // a*bh
                    MMA(acc1[mt][nt], ah, bl[nt], bl[nt + 2]);   // a*bl
                }
            }
        }

        // ---- D1 epilogue: bias + relu -> A2 (single fp16, parity-permuted) ----
        #pragma unroll
        for (int mt = 0; mt < 2; mt++) {
            #pragma unroll
            for (int nt = 0; nt < 2; nt++) {
                int r0 = 32 * wm1 + 16 * mt + g;
                int cb = (32 * pg + 16 * wn1 + 8 * nt + 2 * tg) * 2;
                float f00 = fmaxf(acc1[mt][nt][0] + b2a[nt], 0.f);
                float f01 = fmaxf(acc1[mt][nt][1] + b2c[nt], 0.f);
                float f10 = fmaxf(acc1[mt][nt][2] + b2a[nt], 0.f);
                float f11 = fmaxf(acc1[mt][nt][3] + b2c[nt], 0.f);
                uint32_t u0 = (uint32_t)h16(f00) | ((uint32_t)h16(f01) << 16);
                uint32_t u1 = (uint32_t)h16(f10) | ((uint32_t)h16(f11) << 16);
                *(uint32_t*)(smc + A2 + r0 * S + cb)       = u0;
                *(uint32_t*)(smc + A2 + (r0 + 8) * S + cb) = u1;
            }
        }
        __syncthreads();

        // ========= GEMM2: [64x64] = A2[64x64] * B2^T =========
        float acc2[2][2][4];
        #pragma unroll
        for (int mt = 0; mt < 2; mt++)
            #pragma unroll
            for (int nt = 0; nt < 2; nt++)
                #pragma unroll
                for (int i = 0; i < 4; i++) acc2[mt][nt][i] = 0.f;

        #pragma unroll
        for (int kt = 0; kt < 4; kt++) {
            uint32_t bh[4], bl[4];
            LDSM4(bh, b2b + kt * 32);
            LDSM4(bl, b2b + kt * 32 + (B2LO - B2HI));
            #pragma unroll
            for (int mt = 0; mt < 2; mt++) {
                uint32_t ah[4];
                LDSM4(ah, a2b + mt * (16 * S) + kt * 32);
                #pragma unroll
                for (int nt = 0; nt < 2; nt++) {
                    MMA(acc2[mt][nt], ah, bh[nt], bh[nt + 2]);
                    MMA(acc2[mt][nt], ah, bl[nt], bl[nt + 2]);
                }
            }
        }

        // ---- D2 epilogue: + bp -> out ----
        #pragma unroll
        for (int mt = 0; mt < 2; mt++) {
            #pragma unroll
            for (int nt = 0; nt < 2; nt++) {
                size_t r0 = (size_t)tile * 64 + 32 * wm2 + 16 * mt + g;
                int ncol = 16 * wn2 + 8 * nt + 2 * tg;
                float2 v0 = make_float2(acc2[mt][nt][0] + bpv[nt][0], acc2[mt][nt][1] + bpv[nt][1]);
                float2 v1 = make_float2(acc2[mt][nt][2] + bpv[nt][0], acc2[mt][nt][3] + bpv[nt][1]);
                *(float2*)(out + r0 * 64 + ncol)       = v0;
                *(float2*)(out + (r0 + 8) * 64 + ncol) = v1;
            }
        }
        __syncthreads();   // protect A tiles before next tile's writes
    }
}

extern "C" void kernel_launch(void* const* d_in, const int* in_sizes, int n_in,
                              void* d_out, int out_size)
{
    const float* x  = (const float*)d_in[0];
    const float* W1 = (const float*)d_in[1];
    const float* b1 = (const float*)d_in[2];
    const float* W2 = (const float*)d_in[3];
    const float* b2 = (const float*)d_in[4];
    const float* Wp = (const float*)d_in[5];
    const float* bp = (const float*)d_in[6];
    float* out = (float*)d_out;

    cudaFuncSetAttribute(cnn_encoder_mma5,
                         cudaFuncAttributeMaxDynamicSharedMemorySize, SMEM_BYTES);

    cnn_encoder_mma5<<<GRID, THREADS, SMEM_BYTES>>>(x, W1, b1, W2, b2, Wp, bp, out);
}

// round 10
// speedup vs baseline: 4.4360x; 1.1275x over previous
#include <cuda_runtime.h>
#include <cuda_fp16.h>
#include <cstdint>
#include <cstddef>

#define THREADS 256
#define GRID    592
#define NTILES  8192          // 524288 rows / 64

#define S 144                 // row stride (bytes), conflict-free
// smem byte offsets (per CTA, tile M=64)
#define AP0   0               // A0: 64 x 64 fp16 (h1 pos j)
#define AP1   9216            // A1: 64 x 64 fp16 (h1 pos 1+j)
#define A2    18432           // h2 parity-permuted: col = c2 + 32p
#define B1    27648           // W2 reshaped 32 x 64 (fp16, no split)
#define B2HI  32256           // Wp column-permuted 64 x 64 (fp16 hi/lo)
#define B2LO  41472
#define CST   50688           // floats: W1[128], b1[32]
#define SMEM_BYTES (50688 + 160 * 4)

static __device__ __forceinline__ uint32_t smem_u32(const void* p) {
    uint32_t a;
    asm("{ .reg .u64 t; cvta.to.shared.u64 t, %1; cvt.u32.u64 %0, t; }" : "=r"(a) : "l"(p));
    return a;
}
static __device__ __forceinline__ uint16_t h16(float v) {
    __half h = __float2half_rn(v);
    return reinterpret_cast<uint16_t&>(h);
}
// packed pair: lo half = vlo, hi half = vhi (single F2FP instr)
static __device__ __forceinline__ uint32_t h2pack(float vlo, float vhi) {
    uint32_t r;
    asm("cvt.rn.f16x2.f32 %0, %1, %2;" : "=r"(r) : "f"(vhi), "f"(vlo));
    return r;
}
static __device__ __forceinline__ void hsplit(float v, uint16_t& h, uint16_t& l) {
    __half hh = __float2half_rn(v);
    float vh = __half2float(hh);
    __half hl = __float2half_rn(v - vh);
    h = reinterpret_cast<uint16_t&>(hh);
    l = reinterpret_cast<uint16_t&>(hl);
}

#define LDSM4(r, addr) \
    asm volatile("ldmatrix.sync.aligned.m8n8.x4.shared.b16 {%0,%1,%2,%3}, [%4];" \
        : "=r"((r)[0]), "=r"((r)[1]), "=r"((r)[2]), "=r"((r)[3]) : "r"(addr))

#define MMA(d, a, b0, b1) \
    asm volatile("mma.sync.aligned.m16n8k16.row.col.f32.f16.f16.f32 " \
        "{%0,%1,%2,%3}, {%4,%5,%6,%7}, {%8,%9}, {%0,%1,%2,%3};" \
        : "+f"((d)[0]), "+f"((d)[1]), "+f"((d)[2]), "+f"((d)[3]) \
        : "r"((a)[0]), "r"((a)[1]), "r"((a)[2]), "r"((a)[3]), "r"(b0), "r"(b1))

__global__ __launch_bounds__(THREADS, 4)
void cnn_encoder_mma6(const float* __restrict__ x,
                      const float* __restrict__ W1, const float* __restrict__ b1,
                      const float* __restrict__ W2, const float* __restrict__ b2,
                      const float* __restrict__ Wp, const float* __restrict__ bp,
                      float* __restrict__ out)
{
    extern __shared__ char smc[];
    const uint32_t sb = smem_u32(smc);
    float* cst = (float*)(smc + CST);   // W1[0:128) b1[128:160)

    const int t    = threadIdx.x;
    const int w    = t >> 5;
    const int lane = t & 31;
    const int g    = lane >> 2;
    const int tg   = lane & 3;
    // GEMM1 roles: parity group + 2m x 2n grid
    const int pg   = w >> 2;
    const int wm1  = w & 1;
    const int wn1  = (w >> 1) & 1;
    // GEMM2 roles: 2m x 4n grid
    const int wm2  = w & 1;
    const int wn2  = w >> 1;

    // ---- stage consts + B tiles (once) ----
    if (t < 128) cst[t] = W1[t];
    if (t < 32)  cst[128 + t] = b1[t];

    // B1 = W2 reshaped [c2=32][k=64], single fp16
    for (int i = t; i < 32 * 64; i += THREADS) {
        int c2 = i >> 6, kk = i & 63;
        *(uint16_t*)(smc + B1 + c2 * S + kk * 2) = h16(W2[i]);
    }
    // B2[o][kk] = Wp[o][2*(kk&31) + (kk>>5)]  (parity-permuted columns), fp16 hi/lo
    for (int i = t; i < 64 * 64; i += THREADS) {
        int o = i >> 6, kk = i & 63;
        uint16_t h, l; hsplit(Wp[o * 64 + 2 * (kk & 31) + (kk >> 5)], h, l);
        *(uint16_t*)(smc + B2HI + o * S + kk * 2) = h;
        *(uint16_t*)(smc + B2LO + o * S + kk * 2) = l;
    }

    // per-thread biases
    float b2a[2], b2c[2], bpv[2][2];
    #pragma unroll
    for (int nt = 0; nt < 2; nt++) {
        b2a[nt] = b2[16 * wn1 + 8 * nt + 2 * tg];
        b2c[nt] = b2[16 * wn1 + 8 * nt + 2 * tg + 1];
        bpv[nt][0] = bp[16 * wn2 + 8 * nt + 2 * tg];
        bpv[nt][1] = bp[16 * wn2 + 8 * nt + 2 * tg + 1];
    }

    // ldmatrix lane addressing (validated pattern)
    const int mat  = lane >> 3;
    const int lrow = (lane & 7) + 8 * (mat & 1);
    const int kby  = 16 * (mat >> 1);
    const uint32_t a1b = sb + (pg ? AP1 : AP0) + (32 * wm1 + lrow) * S + kby;
    const uint32_t b1b = sb + B1 + (16 * wn1 + lrow) * S + kby;
    const uint32_t a2b = sb + A2 + (32 * wm2 + lrow) * S + kby;
    const uint32_t b2b = sb + B2HI + (16 * wn2 + lrow) * S + kby;

    const int row = t & 63;       // conv: row within 64-row tile
    const int qh  = t >> 6;       // conv: 8-channel group 0..3

    __syncthreads();

    for (int tile = blockIdx.x; tile < NTILES; tile += GRID) {
        // ================= conv1 -> A0/A1 (single fp16, packed cvt) =================
        {
            const float4* xr = (const float4*)(x + ((size_t)tile * 64 + row) * 8);
            float4 xa = xr[0], xb = xr[1];
            const float x0 = xa.x, x1 = xa.y, x2 = xa.z, x3 = xa.w;
            const float x4 = xb.x, x5 = xb.y, x6 = xb.z, x7 = xb.w;

            uint32_t a0[8], a1[8];
            #pragma unroll
            for (int u = 0; u < 8; u++) {
                int c1 = 8 * qh + u;
                float4 wv = ((const float4*)cst)[c1];
                float bb  = cst[128 + c1];
                float p0 = fmaxf(bb + wv.x * x0 + wv.y * x1 + wv.z * x4 + wv.w * x5, 0.f);
                float p1 = fmaxf(bb + wv.x * x1 + wv.y * x2 + wv.z * x5 + wv.w * x6, 0.f);
                float p2 = fmaxf(bb + wv.x * x2 + wv.y * x3 + wv.z * x6 + wv.w * x7, 0.f);
                a0[u] = h2pack(p0, p1);   // A0 pair (p0,p1)
                a1[u] = h2pack(p1, p2);   // A1 pair (p1,p2)
            }
            char* base = smc + row * S + 32 * qh;
            *(uint4*)(base + AP0)      = make_uint4(a0[0], a0[1], a0[2], a0[3]);
            *(uint4*)(base + AP0 + 16) = make_uint4(a0[4], a0[5], a0[6], a0[7]);
            *(uint4*)(base + AP1)      = make_uint4(a1[0], a1[1], a1[2], a1[3]);
            *(uint4*)(base + AP1 + 16) = make_uint4(a1[4], a1[5], a1[6], a1[7]);
        }
        __syncthreads();

        // ========= GEMM1 (parity pg): [64x32] = A_pg[64x64] * B1^T  (single B) =========
        float acc1[2][2][4];
        #pragma unroll
        for (int mt = 0; mt < 2; mt++)
            #pragma unroll
            for (int nt = 0; nt < 2; nt++)
                #pragma unroll
                for (int i = 0; i < 4; i++) acc1[mt][nt][i] = 0.f;

        #pragma unroll
        for (int kt = 0; kt < 4; kt++) {
            uint32_t bh[4];
            LDSM4(bh, b1b + kt * 32);
            #pragma unroll
            for (int mt = 0; mt < 2; mt++) {
                uint32_t ah[4];
                LDSM4(ah, a1b + mt * (16 * S) + kt * 32);
                #pragma unroll
                for (int nt = 0; nt < 2; nt++)
                    MMA(acc1[mt][nt], ah, bh[nt], bh[nt + 2]);
            }
        }

        // ---- D1 epilogue: bias + relu -> A2 (single fp16, parity-permuted) ----
        #pragma unroll
        for (int mt = 0; mt < 2; mt++) {
            #pragma unroll
            for (int nt = 0; nt < 2; nt++) {
                int r0 = 32 * wm1 + 16 * mt + g;
                int cb = (32 * pg + 16 * wn1 + 8 * nt + 2 * tg) * 2;
                float f00 = fmaxf(acc1[mt][nt][0] + b2a[nt], 0.f);
                float f01 = fmaxf(acc1[mt][nt][1] + b2c[nt], 0.f);
                float f10 = fmaxf(acc1[mt][nt][2] + b2a[nt], 0.f);
                float f11 = fmaxf(acc1[mt][nt][3] + b2c[nt], 0.f);
                *(uint32_t*)(smc + A2 + r0 * S + cb)       = h2pack(f00, f01);
                *(uint32_t*)(smc + A2 + (r0 + 8) * S + cb) = h2pack(f10, f11);
            }
        }
        __syncthreads();

        // ========= GEMM2: [64x64] = A2[64x64] * B2^T  (B hi/lo split) =========
        float acc2[2][2][4];
        #pragma unroll
        for (int mt = 0; mt < 2; mt++)
            #pragma unroll
            for (int nt = 0; nt < 2; nt++)
                #pragma unroll
                for (int i = 0; i < 4; i++) acc2[mt][nt][i] = 0.f;

        #pragma unroll
        for (int kt = 0; kt < 4; kt++) {
            uint32_t bh[4], bl[4];
            LDSM4(bh, b2b + kt * 32);
            LDSM4(bl, b2b + kt * 32 + (B2LO - B2HI));
            #pragma unroll
            for (int mt = 0; mt < 2; mt++) {
                uint32_t ah[4];
                LDSM4(ah, a2b + mt * (16 * S) + kt * 32);
                #pragma unroll
                for (int nt = 0; nt < 2; nt++) {
                    MMA(acc2[mt][nt], ah, bh[nt], bh[nt + 2]);
                    MMA(acc2[mt][nt], ah, bl[nt], bl[nt + 2]);
                }
            }
        }

        // ---- D2 epilogue: + bp -> out ----
        #pragma unroll
        for (int mt = 0; mt < 2; mt++) {
            #pragma unroll
            for (int nt = 0; nt < 2; nt++) {
                size_t r0 = (size_t)tile * 64 + 32 * wm2 + 16 * mt + g;
                int ncol = 16 * wn2 + 8 * nt + 2 * tg;
                float2 v0 = make_float2(acc2[mt][nt][0] + bpv[nt][0], acc2[mt][nt][1] + bpv[nt][1]);
                float2 v1 = make_float2(acc2[mt][nt][2] + bpv[nt][0], acc2[mt][nt][3] + bpv[nt][1]);
                *(float2*)(out + r0 * 64 + ncol)       = v0;
                *(float2*)(out + (r0 + 8) * 64 + ncol) = v1;
            }
        }
        __syncthreads();   // protect A tiles before next tile's writes
    }
}

extern "C" void kernel_launch(void* const* d_in, const int* in_sizes, int n_in,
                              void* d_out, int out_size)
{
    const float* x  = (const float*)d_in[0];
    const float* W1 = (const float*)d_in[1];
    const float* b1 = (const float*)d_in[2];
    const float* W2 = (const float*)d_in[3];
    const float* b2 = (const float*)d_in[4];
    const float* Wp = (const float*)d_in[5];
    const float* bp = (const float*)d_in[6];
    float* out = (float*)d_out;

    cudaFuncSetAttribute(cnn_encoder_mma6,
                         cudaFuncAttributeMaxDynamicSharedMemorySize, SMEM_BYTES);

    cnn_encoder_mma6<<<GRID, THREADS, SMEM_BYTES>>>(x, W1, b1, W2, b2, Wp, bp, out);
}

// round 11
// speedup vs baseline: 4.4771x; 1.0093x over previous
#include <cuda_runtime.h>
#include <cuda_fp16.h>
#include <cstdint>
#include <cstddef>

#define THREADS 256
#define GRID    444
#define NTILES  8192          // 524288 rows / 64

#define S 144                 // row stride (bytes), conflict-free
// smem byte offsets (per CTA, tile M=64)
#define AP0   0               // A0: 64 x 64 fp16 (h1 pos j)
#define AP1   9216            // A1: 64 x 64 fp16 (h1 pos 1+j)
#define A2    18432           // h2 parity-permuted: col = c2 + 32p
#define B1    27648           // W2 reshaped 32 x 64 (fp16) — init staging only
#define B2HI  32256           // Wp column-permuted 64 x 64 (fp16 hi/lo) — init staging only
#define B2LO  41472
#define CST   50688           // floats: W1[128], b1[32]
#define SMEM_BYTES (50688 + 160 * 4)

static __device__ __forceinline__ uint32_t smem_u32(const void* p) {
    uint32_t a;
    asm("{ .reg .u64 t; cvta.to.shared.u64 t, %1; cvt.u32.u64 %0, t; }" : "=r"(a) : "l"(p));
    return a;
}
static __device__ __forceinline__ uint16_t h16(float v) {
    __half h = __float2half_rn(v);
    return reinterpret_cast<uint16_t&>(h);
}
// packed pair: lo half = vlo, hi half = vhi (single F2FP instr)
static __device__ __forceinline__ uint32_t h2pack(float vlo, float vhi) {
    uint32_t r;
    asm("cvt.rn.f16x2.f32 %0, %1, %2;" : "=r"(r) : "f"(vhi), "f"(vlo));
    return r;
}
static __device__ __forceinline__ void hsplit(float v, uint16_t& h, uint16_t& l) {
    __half hh = __float2half_rn(v);
    float vh = __half2float(hh);
    __half hl = __float2half_rn(v - vh);
    h = reinterpret_cast<uint16_t&>(hh);
    l = reinterpret_cast<uint16_t&>(hl);
}

#define LDSM4(r, addr) \
    asm volatile("ldmatrix.sync.aligned.m8n8.x4.shared.b16 {%0,%1,%2,%3}, [%4];" \
        : "=r"((r)[0]), "=r"((r)[1]), "=r"((r)[2]), "=r"((r)[3]) : "r"(addr))

#define MMA(d, a, b0, b1) \
    asm volatile("mma.sync.aligned.m16n8k16.row.col.f32.f16.f16.f32 " \
        "{%0,%1,%2,%3}, {%4,%5,%6,%7}, {%8,%9}, {%0,%1,%2,%3};" \
        : "+f"((d)[0]), "+f"((d)[1]), "+f"((d)[2]), "+f"((d)[3]) \
        : "r"((a)[0]), "r"((a)[1]), "r"((a)[2]), "r"((a)[3]), "r"(b0), "r"(b1))

__global__ __launch_bounds__(THREADS, 3)
void cnn_encoder_mma7(const float* __restrict__ x,
                      const float* __restrict__ W1, const float* __restrict__ b1,
                      const float* __restrict__ W2, const float* __restrict__ b2,
                      const float* __restrict__ Wp, const float* __restrict__ bp,
                      float* __restrict__ out)
{
    extern __shared__ char smc[];
    const uint32_t sb = smem_u32(smc);
    float* cst = (float*)(smc + CST);   // W1[0:128) b1[128:160)

    const int t    = threadIdx.x;
    const int w    = t >> 5;
    const int lane = t & 31;
    const int g    = lane >> 2;
    const int tg   = lane & 3;
    // GEMM1 roles: parity group + 2m x 2n grid
    const int pg   = w >> 2;
    const int wm1  = w & 1;
    const int wn1  = (w >> 1) & 1;
    // GEMM2 roles: 2m x 4n grid
    const int wm2  = w & 1;
    const int wn2  = w >> 1;

    // ---- stage consts + B tiles (once) ----
    if (t < 128) cst[t] = W1[t];
    if (t < 32)  cst[128 + t] = b1[t];

    // B1 = W2 reshaped [c2=32][k=64], single fp16
    for (int i = t; i < 32 * 64; i += THREADS) {
        int c2 = i >> 6, kk = i & 63;
        *(uint16_t*)(smc + B1 + c2 * S + kk * 2) = h16(W2[i]);
    }
    // B2[o][kk] = Wp[o][2*(kk&31) + (kk>>5)]  (parity-permuted columns), fp16 hi/lo
    for (int i = t; i < 64 * 64; i += THREADS) {
        int o = i >> 6, kk = i & 63;
        uint16_t h, l; hsplit(Wp[o * 64 + 2 * (kk & 31) + (kk >> 5)], h, l);
        *(uint16_t*)(smc + B2HI + o * S + kk * 2) = h;
        *(uint16_t*)(smc + B2LO + o * S + kk * 2) = l;
    }

    // per-thread biases
    float b2a[2], b2c[2], bpv[2][2];
    #pragma unroll
    for (int nt = 0; nt < 2; nt++) {
        b2a[nt] = b2[16 * wn1 + 8 * nt + 2 * tg];
        b2c[nt] = b2[16 * wn1 + 8 * nt + 2 * tg + 1];
        bpv[nt][0] = bp[16 * wn2 + 8 * nt + 2 * tg];
        bpv[nt][1] = bp[16 * wn2 + 8 * nt + 2 * tg + 1];
    }

    // ldmatrix lane addressing (validated pattern)
    const int mat  = lane >> 3;
    const int lrow = (lane & 7) + 8 * (mat & 1);
    const int kby  = 16 * (mat >> 1);
    const uint32_t a1b = sb + (pg ? AP1 : AP0) + (32 * wm1 + lrow) * S + kby;
    const uint32_t b1b = sb + B1 + (16 * wn1 + lrow) * S + kby;
    const uint32_t a2b = sb + A2 + (32 * wm2 + lrow) * S + kby;
    const uint32_t b2b = sb + B2HI + (16 * wn2 + lrow) * S + kby;

    const int row = t & 63;       // conv: row within 64-row tile
    const int qh  = t >> 6;       // conv: 8-channel group 0..3

    __syncthreads();

    // ---- hoist ALL B fragments into persistent registers (tile-invariant) ----
    uint32_t b1f[4][4], b2fh[4][4], b2fl[4][4];
    #pragma unroll
    for (int kt = 0; kt < 4; kt++) {
        LDSM4(b1f[kt],  b1b + kt * 32);
        LDSM4(b2fh[kt], b2b + kt * 32);
        LDSM4(b2fl[kt], b2b + kt * 32 + (B2LO - B2HI));
    }

    for (int tile = blockIdx.x; tile < NTILES; tile += GRID) {
        // ================= conv1 -> A0/A1 (single fp16, packed cvt) =================
        {
            const float4* xr = (const float4*)(x + ((size_t)tile * 64 + row) * 8);
            float4 xa = xr[0], xb = xr[1];
            const float x0 = xa.x, x1 = xa.y, x2 = xa.z, x3 = xa.w;
            const float x4 = xb.x, x5 = xb.y, x6 = xb.z, x7 = xb.w;

            uint32_t a0[8], a1[8];
            #pragma unroll
            for (int u = 0; u < 8; u++) {
                int c1 = 8 * qh + u;
                float4 wv = ((const float4*)cst)[c1];
                float bb  = cst[128 + c1];
                float p0 = fmaxf(bb + wv.x * x0 + wv.y * x1 + wv.z * x4 + wv.w * x5, 0.f);
                float p1 = fmaxf(bb + wv.x * x1 + wv.y * x2 + wv.z * x5 + wv.w * x6, 0.f);
                float p2 = fmaxf(bb + wv.x * x2 + wv.y * x3 + wv.z * x6 + wv.w * x7, 0.f);
                a0[u] = h2pack(p0, p1);   // A0 pair (p0,p1)
                a1[u] = h2pack(p1, p2);   // A1 pair (p1,p2)
            }
            char* base = smc + row * S + 32 * qh;
            *(uint4*)(base + AP0)      = make_uint4(a0[0], a0[1], a0[2], a0[3]);
            *(uint4*)(base + AP0 + 16) = make_uint4(a0[4], a0[5], a0[6], a0[7]);
            *(uint4*)(base + AP1)      = make_uint4(a1[0], a1[1], a1[2], a1[3]);
            *(uint4*)(base + AP1 + 16) = make_uint4(a1[4], a1[5], a1[6], a1[7]);
        }
        __syncthreads();

        // ========= GEMM1 (parity pg): [64x32] = A_pg[64x64] * B1^T  (B in regs) =========
        float acc1[2][2][4];
        #pragma unroll
        for (int mt = 0; mt < 2; mt++)
            #pragma unroll
            for (int nt = 0; nt < 2; nt++)
                #pragma unroll
                for (int i = 0; i < 4; i++) acc1[mt][nt][i] = 0.f;

        #pragma unroll
        for (int kt = 0; kt < 4; kt++) {
            #pragma unroll
            for (int mt = 0; mt < 2; mt++) {
                uint32_t ah[4];
                LDSM4(ah, a1b + mt * (16 * S) + kt * 32);
                #pragma unroll
                for (int nt = 0; nt < 2; nt++)
                    MMA(acc1[mt][nt], ah, b1f[kt][nt], b1f[kt][nt + 2]);
            }
        }

        // ---- D1 epilogue: bias + relu -> A2 (single fp16, parity-permuted) ----
        #pragma unroll
        for (int mt = 0; mt < 2; mt++) {
            #pragma unroll
            for (int nt = 0; nt < 2; nt++) {
                int r0 = 32 * wm1 + 16 * mt + g;
                int cb = (32 * pg + 16 * wn1 + 8 * nt + 2 * tg) * 2;
                float f00 = fmaxf(acc1[mt][nt][0] + b2a[nt], 0.f);
                float f01 = fmaxf(acc1[mt][nt][1] + b2c[nt], 0.f);
                float f10 = fmaxf(acc1[mt][nt][2] + b2a[nt], 0.f);
                float f11 = fmaxf(acc1[mt][nt][3] + b2c[nt], 0.f);
                *(uint32_t*)(smc + A2 + r0 * S + cb)       = h2pack(f00, f01);
                *(uint32_t*)(smc + A2 + (r0 + 8) * S + cb) = h2pack(f10, f11);
            }
        }
        __syncthreads();

        // ========= GEMM2: [64x64] = A2[64x64] * B2^T  (B hi/lo in regs) =========
        float acc2[2][2][4];
        #pragma unroll
        for (int mt = 0; mt < 2; mt++)
            #pragma unroll
            for (int nt = 0; nt < 2; nt++)
                #pragma unroll
                for (int i = 0; i < 4; i++) acc2[mt][nt][i] = 0.f;

        #pragma unroll
        for (int kt = 0; kt < 4; kt++) {
            #pragma unroll
            for (int mt = 0; mt < 2; mt++) {
                uint32_t ah[4];
                LDSM4(ah, a2b + mt * (16 * S) + kt * 32);
                #pragma unroll
                for (int nt = 0; nt < 2; nt++) {
                    MMA(acc2[mt][nt], ah, b2fh[kt][nt], b2fh[kt][nt + 2]);
                    MMA(acc2[mt][nt], ah, b2fl[kt][nt], b2fl[kt][nt + 2]);
                }
            }
        }

        // ---- D2 epilogue: + bp -> out ----
        #pragma unroll
        for (int mt = 0; mt < 2; mt++) {
            #pragma unroll
            for (int nt = 0; nt < 2; nt++) {
                size_t r0 = (size_t)tile * 64 + 32 * wm2 + 16 * mt + g;
                int ncol = 16 * wn2 + 8 * nt + 2 * tg;
                float2 v0 = make_float2(acc2[mt][nt][0] + bpv[nt][0], acc2[mt][nt][1] + bpv[nt][1]);
                float2 v1 = make_float2(acc2[mt][nt][2] + bpv[nt][0], acc2[mt][nt][3] + bpv[nt][1]);
                *(float2*)(out + r0 * 64 + ncol)       = v0;
                *(float2*)(out + (r0 + 8) * 64 + ncol) = v1;
            }
        }
        __syncthreads();   // protect A tiles before next tile's writes
    }
}

extern "C" void kernel_launch(void* const* d_in, const int* in_sizes, int n_in,
                              void* d_out, int out_size)
{
    const float* x  = (const float*)d_in[0];
    const float* W1 = (const float*)d_in[1];
    const float* b1 = (const float*)d_in[2];
    const float* W2 = (const float*)d_in[3];
    const float* b2 = (const float*)d_in[4];
    const float* Wp = (const float*)d_in[5];
    const float* bp = (const float*)d_in[6];
    float* out = (float*)d_out;

    cudaFuncSetAttribute(cnn_encoder_mma7,
                         cudaFuncAttributeMaxDynamicSharedMemorySize, SMEM_BYTES);

    cnn_encoder_mma7<<<GRID, THREADS, SMEM_BYTES>>>(x, W1, b1, W2, b2, Wp, bp, out);
}